// round 11
// baseline (speedup 1.0000x reference)
#include <cuda_runtime.h>
#include <cstdint>
#include <cstddef>

#define TT   2048
#define DD   1024
#define NTOK 8192      // B*T
#define KVN  48
#define DIN  1408
#define NN   2048      // 2*D
#define NK8  176       // DIN/8

// ---------------- scratch (device globals: allocation-free) ----------------
__device__ float g_blog[NTOK];
__device__ float g_keylog[NTOK * KVN];
__device__ float g_lnh[(size_t)NTOK * DD];
__device__ float g_fa[(size_t)NTOK * DIN];    // film_in in A-fragment order
__device__ float g_bwf[(size_t)NN * DIN];     // film_w tf32, permuted, PAIRED B-frag order

__device__ __forceinline__ float rna_tf32(float x) {
    uint32_t u;
    asm("cvt.rna.tf32.f32 %0, %1;" : "=r"(u) : "f"(x));
    return __uint_as_float(u);
}

__device__ __forceinline__ void cp16(uint32_t dst, const void* src) {
    asm volatile("cp.async.cg.shared.global [%0], [%1], 16;" :: "r"(dst), "l"(src));
}
#define CP_COMMIT() asm volatile("cp.async.commit_group;")
#define CP_WAIT1()  asm volatile("cp.async.wait_group 1;")

#define MMA_TF32(d0,d1,d2,d3,a0,a1,a2,a3,b0,b1)                              \
  asm volatile("mma.sync.aligned.m16n8k8.row.col.f32.tf32.tf32.f32 "         \
    "{%0,%1,%2,%3},{%4,%5,%6,%7},{%8,%9},{%0,%1,%2,%3};\n"                   \
    : "+f"(d0), "+f"(d1), "+f"(d2), "+f"(d3)                                 \
    : "r"(a0), "r"(a1), "r"(a2), "r"(a3), "r"(b0), "r"(b1))

// ---------------- K1: fused [k1 | roundBt] ---------------------------------
// blocks [0,256): key logits + boundary logits for 32 tokens each
// blocks [256, 256+2816): film_w -> tf32, permuted, PAIRED B-frag superblocks
#define K1_BLOCKS 256
#define RB_BLOCKS 2816    // (128 * NK8) / 8
__global__ __launch_bounds__(256) void k1(const float* __restrict__ h,
                                          const float* __restrict__ key_w,
                                          const float* __restrict__ key_b,
                                          const float* __restrict__ bound_w,
                                          const float* __restrict__ bound_b,
                                          const float* __restrict__ film_w) {
    if (blockIdx.x >= K1_BLOCKS) {
        // ---- roundBt path ----
        int w = (blockIdx.x - K1_BLOCKS) * 8 + (threadIdx.x >> 5);
        int lane = threadIdx.x & 31;
        int kt8 = w % NK8, P = w / NK8;                // P < 128
        int prow0 = P * 16 + (lane >> 2);
        int prow1 = prow0 + 8;
        int k = kt8 * 8 + (lane & 3);
        int g20 = prow0 >> 7, r0 = prow0 & 127;
        int n0 = (r0 < 64) ? (g20 * 64 + r0) : (1024 + g20 * 64 + (r0 - 64));
        int g21 = prow1 >> 7, r1 = prow1 & 127;
        int n1 = (r1 < 64) ? (g21 * 64 + r1) : (1024 + g21 * 64 + (r1 - 64));
        float4 o;
        o.x = rna_tf32(film_w[(size_t)k * NN + n0]);
        o.y = rna_tf32(film_w[(size_t)(k + 4) * NN + n0]);
        o.z = rna_tf32(film_w[(size_t)k * NN + n1]);
        o.w = rna_tf32(film_w[(size_t)(k + 4) * NN + n1]);
        *(float4*)&g_bwf[((size_t)w << 7) + (lane << 2)] = o;
        return;
    }
    // ---- k1 path ----
    __shared__ float hs[32][128];
    __shared__ float ws[128][49];
    __shared__ float bw[128];
    int tid = threadIdx.x;
    int tok0 = blockIdx.x * 32;
    int tg = tid >> 4;
    int ob = (tid & 15) * 3;
    int btok = tid >> 3;
    int be0 = (tid & 7) * 16;
    float a00 = 0.f, a01 = 0.f, a02 = 0.f, a10 = 0.f, a11 = 0.f, a12 = 0.f;
    float bacc = 0.f;
    for (int c = 0; c < 8; c++) {
#pragma unroll
        for (int k2 = 0; k2 < 4; k2++) {
            int idx = tid + k2 * 256;
            int row = idx >> 5, colv = idx & 31;
            *(float4*)&hs[row][colv * 4] =
                *(const float4*)&h[(size_t)(tok0 + row) * DD + c * 128 + colv * 4];
        }
#pragma unroll
        for (int k2 = 0; k2 < 24; k2++) {
            int idx = tid + k2 * 256;
            int d = idx / 48, kk = idx - d * 48;
            ws[d][kk] = key_w[(size_t)(c * 128 + d) * KVN + kk];
        }
        if (tid < 128) bw[tid] = bound_w[c * 128 + tid];
        __syncthreads();
#pragma unroll 4
        for (int d4 = 0; d4 < 32; d4++) {
            float4 ha = *(float4*)&hs[tg][d4 * 4];
            float4 hb = *(float4*)&hs[tg + 16][d4 * 4];
            float hav[4] = {ha.x, ha.y, ha.z, ha.w};
            float hbv[4] = {hb.x, hb.y, hb.z, hb.w};
#pragma unroll
            for (int j = 0; j < 4; j++) {
                int d = d4 * 4 + j;
                float w0 = ws[d][ob], w1 = ws[d][ob + 1], w2 = ws[d][ob + 2];
                a00 += hav[j] * w0; a01 += hav[j] * w1; a02 += hav[j] * w2;
                a10 += hbv[j] * w0; a11 += hbv[j] * w1; a12 += hbv[j] * w2;
            }
        }
        {
            float p = 0.f;
#pragma unroll
            for (int e = 0; e < 16; e++) p += hs[btok][be0 + e] * bw[be0 + e];
#pragma unroll
            for (int o = 4; o; o >>= 1) p += __shfl_xor_sync(0xffffffffu, p, o);
            bacc += p;
        }
        __syncthreads();
    }
    float kb0 = key_b[ob], kb1 = key_b[ob + 1], kb2 = key_b[ob + 2];
    size_t o0 = (size_t)(tok0 + tg) * KVN + ob;
    size_t o1 = (size_t)(tok0 + tg + 16) * KVN + ob;
    g_keylog[o0] = a00 + kb0; g_keylog[o0 + 1] = a01 + kb1; g_keylog[o0 + 2] = a02 + kb2;
    g_keylog[o1] = a10 + kb0; g_keylog[o1 + 1] = a11 + kb1; g_keylog[o1 + 2] = a12 + kb2;
    if ((tid & 7) == 0) g_blog[tok0 + btok] = bacc + bound_b[0];
}

// ---------------- K3: conv+sigmoid + softmax/ek/eb + two layernorms --------
__global__ __launch_bounds__(256) void k_film(const float* __restrict__ h,
                                              const float* __restrict__ conv_w,
                                              const float* __restrict__ conv_b,
                                              const float* __restrict__ e0,
                                              const float* __restrict__ e1,
                                              const float* __restrict__ key_emb,
                                              const float* __restrict__ ln_in_g,
                                              const float* __restrict__ ln_in_b,
                                              const float* __restrict__ ln_h_g,
                                              const float* __restrict__ ln_h_b) {
    __shared__ float xs[DIN];
    __shared__ float kl[KVN];
    __shared__ float red[20];
    __shared__ float s_bs;
    int tid = threadIdx.x, lane = tid & 31, warp = tid >> 5;
    int token = blockIdx.x;

    if (tid == 0) {
        int b = token >> 11, t = token & (TT - 1);
        float s = 0.f;
#pragma unroll
        for (int j = 0; j < 9; j++) {
            int tt = t + j - 4;
            if (tt >= 0 && tt < TT) s += conv_w[j] * g_blog[b * TT + tt];
        }
        s += conv_b[0];
        s_bs = 1.f / (1.f + __expf(-s));
    }

    float4 hv = *(const float4*)&h[(size_t)token * DD + tid * 4];
    *(float4*)&xs[tid * 4] = hv;
    float ps = hv.x + hv.y + hv.z + hv.w;
    float pq = hv.x * hv.x + hv.y * hv.y + hv.z * hv.z + hv.w * hv.w;

    float s = ps, q = pq;
#pragma unroll
    for (int o = 16; o; o >>= 1) {
        s += __shfl_xor_sync(0xffffffffu, s, o);
        q += __shfl_xor_sync(0xffffffffu, q, o);
    }
    if (lane == 0) { red[warp] = s; red[8 + warp] = q; }
    __syncthreads();
    if (tid == 0) {
        float S = 0.f, Q = 0.f;
        for (int i = 0; i < 8; i++) { S += red[i]; Q += red[8 + i]; }
        red[16] = S; red[17] = Q;
    }
    __syncthreads();
    float muh = red[16] * (1.f / DD);
    float varh = red[17] * (1.f / DD) - muh * muh;
    float rsh = rsqrtf(varh + 1e-5f);
    {
        float4 g4 = *(const float4*)&ln_h_g[tid * 4];
        float4 b4 = *(const float4*)&ln_h_b[tid * 4];
        float4 z4;
        z4.x = (hv.x - muh) * rsh * g4.x + b4.x;
        z4.y = (hv.y - muh) * rsh * g4.y + b4.y;
        z4.z = (hv.z - muh) * rsh * g4.z + b4.z;
        z4.w = (hv.w - muh) * rsh * g4.w + b4.w;
        *(float4*)&g_lnh[(size_t)token * DD + tid * 4] = z4;
    }

    if (tid < KVN) kl[tid] = g_keylog[(size_t)token * KVN + tid];
    __syncthreads();
    if (warp == 0) {
        float m = kl[lane];
        if (lane < 16) m = fmaxf(m, kl[32 + lane]);
#pragma unroll
        for (int o = 16; o; o >>= 1) m = fmaxf(m, __shfl_xor_sync(0xffffffffu, m, o));
        if (lane == 0) red[18] = m;
    }
    __syncthreads();
    float mx = red[18];
    if (tid < KVN) kl[tid] = __expf(kl[tid] - mx);
    __syncthreads();
    if (warp == 0) {
        float sm2 = kl[lane] + (lane < 16 ? kl[32 + lane] : 0.f);
#pragma unroll
        for (int o = 16; o; o >>= 1) sm2 += __shfl_xor_sync(0xffffffffu, sm2, o);
        if (lane == 0) red[19] = 1.f / sm2;
    }
    __syncthreads();
    float sinv = red[19];

    if (tid < 128) {
        float a = 0.f;
#pragma unroll
        for (int k = 0; k < KVN; k++) a += kl[k] * key_emb[k * 128 + tid];
        xs[1280 + tid] = a * sinv;
    }
    float bs = s_bs;
    xs[1024 + tid] = bs * e1[tid] + (1.f - bs) * e0[tid];
    __syncthreads();

    float ts = xs[1024 + tid], tq = ts * ts;
    if (tid < 128) { float v = xs[1280 + tid]; ts += v; tq += v * v; }
    s = ps + ts; q = pq + tq;
#pragma unroll
    for (int o = 16; o; o >>= 1) {
        s += __shfl_xor_sync(0xffffffffu, s, o);
        q += __shfl_xor_sync(0xffffffffu, q, o);
    }
    if (lane == 0) { red[warp] = s; red[8 + warp] = q; }
    __syncthreads();
    if (tid == 0) {
        float S = 0.f, Q = 0.f;
        for (int i = 0; i < 8; i++) { S += red[i]; Q += red[8 + i]; }
        red[16] = S; red[17] = Q;
    }
    __syncthreads();
    float mu = red[16] * (1.f / DIN);
    float var = red[17] * (1.f / DIN) - mu * mu;
    float rs = rsqrtf(var + 1e-5f);
    int mrh = (token >> 3) & 1;
    size_t trow = (size_t)(token >> 4) * NK8;
    int lbase = (token & 7) << 2;
    for (int i = tid; i < DIN; i += 256) {
        float y = (xs[i] - mu) * rs * ln_in_g[i] + ln_in_b[i];
        size_t idx = ((trow + (i >> 3)) << 7) + (((lbase + (i & 3)) << 2) | (mrh + (((i >> 2) & 1) << 1)));
        g_fa[idx] = rna_tf32(y);
    }
}

// ---------------- K4: frag-layout tf32 GEMM + balanced window writer -------
#define STG_F 8192                 // floats per stage
#define SMEM_TOTAL_G (3 * STG_F * 4)
__global__ __launch_bounds__(256, 2) void k_gemm8(const float* __restrict__ bias,
                                                  const float* __restrict__ h,
                                                  float* __restrict__ out) {
    extern __shared__ float sm[];
    uint32_t sb = (uint32_t)__cvta_generic_to_shared(sm);
    int tid = threadIdx.x;
    int bx = blockIdx.x;                 // 0..15
    int m0 = blockIdx.y * 128;
    int warp = tid >> 5, lane = tid & 31;
    int wm = (warp & 1) * 64, wn = (warp >> 1) * 32;
    int grp = lane >> 2, tig = lane & 3;

    float acc[4][4][4];
#pragma unroll
    for (int i = 0; i < 4; i++)
#pragma unroll
        for (int j = 0; j < 4; j++)
#pragma unroll
            for (int r = 0; r < 4; r++) acc[i][j][r] = 0.f;

    int aidx[4], soffA[4], bidx[4], soffB[4];
#pragma unroll
    for (int p = 0; p < 4; p++) {
        int lin = p * 256 + tid;
        int tileA = lin >> 5, chA = lin & 31;          // A: 32 tiles x 512B
        aidx[p] = (((m0 >> 4) + (tileA >> 2)) * NK8 + (tileA & 3)) * 128 + chA * 4;
        soffA[p] = tileA * 512 + chA * 16;
        int tileB = lin >> 5, chB = lin & 31;          // B: 32 superblocks x 512B
        bidx[p] = ((bx * 8 + (tileB >> 2)) * NK8 + (tileB & 3)) * 128 + chB * 4;
        soffB[p] = 16384 + tileB * 512 + chB * 16;
    }

    auto load_stage = [&](int s, int kt) {
        uint32_t base = sb + s * (STG_F * 4);
#pragma unroll
        for (int p = 0; p < 4; p++) {
            cp16(base + soffA[p], g_fa  + (size_t)aidx[p] + (size_t)kt * 512);
            cp16(base + soffB[p], g_bwf + (size_t)bidx[p] + (size_t)kt * 512);
        }
    };

#pragma unroll
    for (int s = 0; s < 2; s++) { load_stage(s, s); CP_COMMIT(); }

    for (int kt = 0; kt < 44; kt++) {
        CP_WAIT1();
        __syncthreads();
        if (kt + 2 < 44) load_stage((kt + 2) % 3, kt + 2);
        CP_COMMIT();
        const float* st = sm + (kt % 3) * STG_F;
#pragma unroll
        for (int kb = 0; kb < 4; kb++) {
            uint4 afr[4];
            uint4 bq[2];
#pragma unroll
            for (int mi = 0; mi < 4; mi++)
                afr[mi] = *(const uint4*)(st + ((((wm >> 4) + mi) << 2) + kb) * 128 + (lane << 2));
#pragma unroll
            for (int np = 0; np < 2; np++)
                bq[np] = *(const uint4*)(st + 4096 + ((((wn >> 4) + np) << 2) + kb) * 128 + (lane << 2));
#pragma unroll
            for (int mi = 0; mi < 4; mi++) {
#pragma unroll
                for (int ni = 0; ni < 4; ni++) {
                    uint32_t b0 = (ni & 1) ? bq[ni >> 1].z : bq[ni >> 1].x;
                    uint32_t b1 = (ni & 1) ? bq[ni >> 1].w : bq[ni >> 1].y;
                    MMA_TF32(acc[mi][ni][0], acc[mi][ni][1], acc[mi][ni][2], acc[mi][ni][3],
                             afr[mi].x, afr[mi].y, afr[mi].z, afr[mi].w, b0, b1);
                }
            }
        }
    }

    // ---- epilogue: gamma -> smem, then beta warps build z -> out slot 0 ----
    __syncthreads();
    float* Gs = sm;                         // [128][68]
    if (wn < 64) {
#pragma unroll
        for (int ni = 0; ni < 4; ni++) {
            int cl = wn + ni * 8 + tig * 2;
            int gcol = bx * 64 + cl;
            float bi0 = bias[gcol], bi1 = bias[gcol + 1];
#pragma unroll
            for (int mi = 0; mi < 4; mi++) {
                int rl = wm + mi * 16 + grp;
                Gs[rl * 68 + cl]       = acc[mi][ni][0] + bi0;
                Gs[rl * 68 + cl + 1]   = acc[mi][ni][1] + bi1;
                Gs[(rl + 8) * 68 + cl]     = acc[mi][ni][2] + bi0;
                Gs[(rl + 8) * 68 + cl + 1] = acc[mi][ni][3] + bi1;
            }
        }
    }
    __syncthreads();
    if (wn >= 64) {
#pragma unroll
        for (int ni = 0; ni < 4; ni++) {
            int cb = wn - 64 + ni * 8 + tig * 2;
            int gcol = bx * 64 + cb;
            float bb0 = bias[1024 + gcol], bb1 = bias[1024 + gcol + 1];
#pragma unroll
            for (int mi = 0; mi < 4; mi++) {
#pragma unroll
                for (int half = 0; half < 2; half++) {
                    int rl = wm + mi * 16 + grp + half * 8;
                    int token = m0 + rl;
                    float2 l2 = *(const float2*)&g_lnh[(size_t)token * DD + gcol];
                    float ga0 = Gs[rl * 68 + cb], ga1 = Gs[rl * 68 + cb + 1];
                    float2 z2;
                    z2.x = l2.x * (1.f + ga0) + acc[mi][ni][half * 2]     + bb0;
                    z2.y = l2.y * (1.f + ga1) + acc[mi][ni][half * 2 + 1] + bb1;
                    __stcs((float2*)&out[(size_t)token * 18432 + gcol], z2);
                }
            }
        }
    }

    // ---- balanced fused window writer ------------------------------------
    // every block: full slot j=bx (out slot 1+bx) for its 128 tokens,
    // plus rows [8*bx, 8*bx+8) of slot j=16 (out slot 17).
    {
        int bb2 = m0 >> 11;
        {
            int j = bx;                               // 0..15
            for (int r = 0; r < 128; r++) {
                int token = m0 + r;
                int t = token & (TT - 1);
                int srct = min(max(t + j - 8, 0), TT - 1);
                float4 v = *(const float4*)&h[((size_t)(bb2 * TT + srct)) * DD + tid * 4];
                __stcs((float4*)&out[(size_t)token * 18432 + (size_t)(1 + j) * DD + tid * 4], v);
            }
        }
        {
            int r0 = bx * 8;                          // slot 17 share
            for (int r = r0; r < r0 + 8; r++) {
                int token = m0 + r;
                int t = token & (TT - 1);
                int srct = min(t + 8, TT - 1);        // j=16 -> t+8, clamped
                float4 v = *(const float4*)&h[((size_t)(bb2 * TT + srct)) * DD + tid * 4];
                __stcs((float4*)&out[(size_t)token * 18432 + (size_t)17 * DD + tid * 4], v);
            }
        }
    }
}

// ---------------------------------------------------------------------------
extern "C" void kernel_launch(void* const* d_in, const int* in_sizes, int n_in,
                              void* d_out, int out_size) {
    const float* h        = (const float*)d_in[0];
    const float* bound_w  = (const float*)d_in[1];
    const float* bound_b  = (const float*)d_in[2];
    const float* conv_w   = (const float*)d_in[3];
    const float* conv_b   = (const float*)d_in[4];
    const float* e0       = (const float*)d_in[5];
    const float* e1       = (const float*)d_in[6];
    const float* key_emb  = (const float*)d_in[7];
    const float* key_w    = (const float*)d_in[8];
    const float* key_b    = (const float*)d_in[9];
    const float* ln_in_g  = (const float*)d_in[10];
    const float* ln_in_b  = (const float*)d_in[11];
    const float* film_w   = (const float*)d_in[12];
    const float* film_b   = (const float*)d_in[13];
    const float* ln_h_g   = (const float*)d_in[14];
    const float* ln_h_b   = (const float*)d_in[15];
    float* out = (float*)d_out;

    cudaFuncSetAttribute(k_gemm8, cudaFuncAttributeMaxDynamicSharedMemorySize, SMEM_TOTAL_G);

    k1     <<<K1_BLOCKS + RB_BLOCKS, 256>>>(h, key_w, key_b, bound_w, bound_b, film_w);
    k_film <<<NTOK, 256>>>(h, conv_w, conv_b, e0, e1, key_emb, ln_in_g, ln_in_b, ln_h_g, ln_h_b);
    k_gemm8<<<dim3(16, NTOK / 128), 256, SMEM_TOTAL_G>>>(film_b, h, out);
}

// round 12
// speedup vs baseline: 1.0237x; 1.0237x over previous
#include <cuda_runtime.h>
#include <cstdint>
#include <cstddef>

#define TT   2048
#define DD   1024
#define NTOK 8192      // B*T
#define KVN  48
#define DIN  1408
#define NN   2048      // 2*D
#define NK8  176       // DIN/8

// ---------------- scratch (device globals: allocation-free) ----------------
__device__ float g_blog[NTOK];
__device__ float g_keylog[NTOK * KVN];
__device__ float g_lnh[(size_t)NTOK * DD];
__device__ float g_fa[(size_t)NTOK * DIN];    // film_in in A-fragment order
__device__ float g_bwf[(size_t)NN * DIN];     // film_w tf32, permuted, PAIRED B-frag order

__device__ __forceinline__ float rna_tf32(float x) {
    uint32_t u;
    asm("cvt.rna.tf32.f32 %0, %1;" : "=r"(u) : "f"(x));
    return __uint_as_float(u);
}

__device__ __forceinline__ void cp16(uint32_t dst, const void* src) {
    asm volatile("cp.async.cg.shared.global [%0], [%1], 16;" :: "r"(dst), "l"(src));
}
#define CP_COMMIT() asm volatile("cp.async.commit_group;")
#define CP_WAIT1()  asm volatile("cp.async.wait_group 1;")

#define MMA_TF32(d0,d1,d2,d3,a0,a1,a2,a3,b0,b1)                              \
  asm volatile("mma.sync.aligned.m16n8k8.row.col.f32.tf32.tf32.f32 "         \
    "{%0,%1,%2,%3},{%4,%5,%6,%7},{%8,%9},{%0,%1,%2,%3};\n"                   \
    : "+f"(d0), "+f"(d1), "+f"(d2), "+f"(d3)                                 \
    : "r"(a0), "r"(a1), "r"(a2), "r"(a3), "r"(b0), "r"(b1))

// ---------------- K0: film_w -> tf32, permuted, PAIRED B-frag superblocks --
__global__ __launch_bounds__(256) void k_roundBt(const float* __restrict__ film_w) {
    int w = blockIdx.x * 8 + (threadIdx.x >> 5);   // superblock id = P*NK8 + kt8
    int lane = threadIdx.x & 31;
    int kt8 = w % NK8, P = w / NK8;                // P < 128
    int prow0 = P * 16 + (lane >> 2);
    int prow1 = prow0 + 8;
    int k = kt8 * 8 + (lane & 3);
    int g20 = prow0 >> 7, r0 = prow0 & 127;
    int n0 = (r0 < 64) ? (g20 * 64 + r0) : (1024 + g20 * 64 + (r0 - 64));
    int g21 = prow1 >> 7, r1 = prow1 & 127;
    int n1 = (r1 < 64) ? (g21 * 64 + r1) : (1024 + g21 * 64 + (r1 - 64));
    float4 o;
    o.x = rna_tf32(film_w[(size_t)k * NN + n0]);
    o.y = rna_tf32(film_w[(size_t)(k + 4) * NN + n0]);
    o.z = rna_tf32(film_w[(size_t)k * NN + n1]);
    o.w = rna_tf32(film_w[(size_t)(k + 4) * NN + n1]);
    *(float4*)&g_bwf[((size_t)w << 7) + (lane << 2)] = o;
}

// ---------------- K1: key logits + boundary logits (float4 wst) ------------
__global__ __launch_bounds__(256) void k1(const float* __restrict__ h,
                                          const float* __restrict__ key_w,
                                          const float* __restrict__ key_b,
                                          const float* __restrict__ bound_w,
                                          const float* __restrict__ bound_b) {
    __shared__ __align__(16) float hs[32][128];
    __shared__ __align__(16) float wst[KVN][132];   // transposed key_w tile
    __shared__ float bw[128];
    int tid = threadIdx.x;
    int tok0 = blockIdx.x * 32;
    int tg = tid >> 4;            // 0..15 -> tokens tg, tg+16
    int ob = (tid & 15) * 3;      // 3 key rows per thread
    int btok = tid >> 3;
    int be0 = (tid & 7) * 16;
    float a00 = 0.f, a01 = 0.f, a02 = 0.f, a10 = 0.f, a11 = 0.f, a12 = 0.f;
    float bacc = 0.f;
    for (int c = 0; c < 8; c++) {
#pragma unroll
        for (int k2 = 0; k2 < 4; k2++) {
            int idx = tid + k2 * 256;
            int row = idx >> 5, colv = idx & 31;
            *(float4*)&hs[row][colv * 4] =
                *(const float4*)&h[(size_t)(tok0 + row) * DD + c * 128 + colv * 4];
        }
#pragma unroll
        for (int k2 = 0; k2 < 24; k2++) {
            int idx = tid + k2 * 256;
            int d = idx / 48, kk = idx - d * 48;
            wst[kk][d] = key_w[(size_t)(c * 128 + d) * KVN + kk];
        }
        if (tid < 128) bw[tid] = bound_w[c * 128 + tid];
        __syncthreads();
        const float4* hpa = (const float4*)&hs[tg][0];
        const float4* hpb = (const float4*)&hs[tg + 16][0];
        const float4* w0p = (const float4*)&wst[ob][0];
        const float4* w1p = (const float4*)&wst[ob + 1][0];
        const float4* w2p = (const float4*)&wst[ob + 2][0];
#pragma unroll 8
        for (int d4 = 0; d4 < 32; d4++) {
            float4 ha = hpa[d4];
            float4 hb = hpb[d4];
            float4 w0 = w0p[d4 * 33 / 33];   // plain index; stride handled below
            w0 = ((const float4*)((const float*)w0p))[0];
            // (see corrected indexing below)
            ha = ha; hb = hb; w0 = w0;
            break;
        }
        // -- corrected vector loop (row stride 132 floats = 33 float4) --
#pragma unroll 8
        for (int d4 = 0; d4 < 32; d4++) {
            float4 ha = *(const float4*)&hs[tg][d4 * 4];
            float4 hb = *(const float4*)&hs[tg + 16][d4 * 4];
            float4 w0 = *(const float4*)&wst[ob][d4 * 4];
            float4 w1 = *(const float4*)&wst[ob + 1][d4 * 4];
            float4 w2 = *(const float4*)&wst[ob + 2][d4 * 4];
            a00 += ha.x * w0.x + ha.y * w0.y + ha.z * w0.z + ha.w * w0.w;
            a01 += ha.x * w1.x + ha.y * w1.y + ha.z * w1.z + ha.w * w1.w;
            a02 += ha.x * w2.x + ha.y * w2.y + ha.z * w2.z + ha.w * w2.w;
            a10 += hb.x * w0.x + hb.y * w0.y + hb.z * w0.z + hb.w * w0.w;
            a11 += hb.x * w1.x + hb.y * w1.y + hb.z * w1.z + hb.w * w1.w;
            a12 += hb.x * w2.x + hb.y * w2.y + hb.z * w2.z + hb.w * w2.w;
        }
        {
            float p = 0.f;
#pragma unroll
            for (int e = 0; e < 16; e++) p += hs[btok][be0 + e] * bw[be0 + e];
#pragma unroll
            for (int o = 4; o; o >>= 1) p += __shfl_xor_sync(0xffffffffu, p, o);
            bacc += p;
        }
        __syncthreads();
    }
    float kb0 = key_b[ob], kb1 = key_b[ob + 1], kb2 = key_b[ob + 2];
    size_t o0 = (size_t)(tok0 + tg) * KVN + ob;
    size_t o1 = (size_t)(tok0 + tg + 16) * KVN + ob;
    g_keylog[o0] = a00 + kb0; g_keylog[o0 + 1] = a01 + kb1; g_keylog[o0 + 2] = a02 + kb2;
    g_keylog[o1] = a10 + kb0; g_keylog[o1 + 1] = a11 + kb1; g_keylog[o1 + 2] = a12 + kb2;
    if ((tid & 7) == 0) g_blog[tok0 + btok] = bacc + bound_b[0];
}

// ---------------- K3: conv+sigmoid + softmax/ek/eb + two layernorms --------
__global__ __launch_bounds__(256) void k_film(const float* __restrict__ h,
                                              const float* __restrict__ conv_w,
                                              const float* __restrict__ conv_b,
                                              const float* __restrict__ e0,
                                              const float* __restrict__ e1,
                                              const float* __restrict__ key_emb,
                                              const float* __restrict__ ln_in_g,
                                              const float* __restrict__ ln_in_b,
                                              const float* __restrict__ ln_h_g,
                                              const float* __restrict__ ln_h_b) {
    __shared__ float xs[DIN];
    __shared__ float kl[KVN];
    __shared__ float red[20];
    __shared__ float s_bs;
    int tid = threadIdx.x, lane = tid & 31, warp = tid >> 5;
    int token = blockIdx.x;

    if (tid == 0) {
        int b = token >> 11, t = token & (TT - 1);
        float s = 0.f;
#pragma unroll
        for (int j = 0; j < 9; j++) {
            int tt = t + j - 4;
            if (tt >= 0 && tt < TT) s += conv_w[j] * g_blog[b * TT + tt];
        }
        s += conv_b[0];
        s_bs = 1.f / (1.f + __expf(-s));
    }

    float4 hv = *(const float4*)&h[(size_t)token * DD + tid * 4];
    *(float4*)&xs[tid * 4] = hv;
    float ps = hv.x + hv.y + hv.z + hv.w;
    float pq = hv.x * hv.x + hv.y * hv.y + hv.z * hv.z + hv.w * hv.w;

    float s = ps, q = pq;
#pragma unroll
    for (int o = 16; o; o >>= 1) {
        s += __shfl_xor_sync(0xffffffffu, s, o);
        q += __shfl_xor_sync(0xffffffffu, q, o);
    }
    if (lane == 0) { red[warp] = s; red[8 + warp] = q; }
    __syncthreads();
    if (tid == 0) {
        float S = 0.f, Q = 0.f;
        for (int i = 0; i < 8; i++) { S += red[i]; Q += red[8 + i]; }
        red[16] = S; red[17] = Q;
    }
    __syncthreads();
    float muh = red[16] * (1.f / DD);
    float varh = red[17] * (1.f / DD) - muh * muh;
    float rsh = rsqrtf(varh + 1e-5f);
    {
        float4 g4 = *(const float4*)&ln_h_g[tid * 4];
        float4 b4 = *(const float4*)&ln_h_b[tid * 4];
        float4 z4;
        z4.x = (hv.x - muh) * rsh * g4.x + b4.x;
        z4.y = (hv.y - muh) * rsh * g4.y + b4.y;
        z4.z = (hv.z - muh) * rsh * g4.z + b4.z;
        z4.w = (hv.w - muh) * rsh * g4.w + b4.w;
        *(float4*)&g_lnh[(size_t)token * DD + tid * 4] = z4;
    }

    if (tid < KVN) kl[tid] = g_keylog[(size_t)token * KVN + tid];
    __syncthreads();
    if (warp == 0) {
        float m = kl[lane];
        if (lane < 16) m = fmaxf(m, kl[32 + lane]);
#pragma unroll
        for (int o = 16; o; o >>= 1) m = fmaxf(m, __shfl_xor_sync(0xffffffffu, m, o));
        if (lane == 0) red[18] = m;
    }
    __syncthreads();
    float mx = red[18];
    if (tid < KVN) kl[tid] = __expf(kl[tid] - mx);
    __syncthreads();
    if (warp == 0) {
        float sm2 = kl[lane] + (lane < 16 ? kl[32 + lane] : 0.f);
#pragma unroll
        for (int o = 16; o; o >>= 1) sm2 += __shfl_xor_sync(0xffffffffu, sm2, o);
        if (lane == 0) red[19] = 1.f / sm2;
    }
    __syncthreads();
    float sinv = red[19];

    if (tid < 128) {
        float a = 0.f;
#pragma unroll
        for (int k = 0; k < KVN; k++) a += kl[k] * key_emb[k * 128 + tid];
        xs[1280 + tid] = a * sinv;
    }
    float bs = s_bs;
    xs[1024 + tid] = bs * e1[tid] + (1.f - bs) * e0[tid];
    __syncthreads();

    float ts = xs[1024 + tid], tq = ts * ts;
    if (tid < 128) { float v = xs[1280 + tid]; ts += v; tq += v * v; }
    s = ps + ts; q = pq + tq;
#pragma unroll
    for (int o = 16; o; o >>= 1) {
        s += __shfl_xor_sync(0xffffffffu, s, o);
        q += __shfl_xor_sync(0xffffffffu, q, o);
    }
    if (lane == 0) { red[warp] = s; red[8 + warp] = q; }
    __syncthreads();
    if (tid == 0) {
        float S = 0.f, Q = 0.f;
        for (int i = 0; i < 8; i++) { S += red[i]; Q += red[8 + i]; }
        red[16] = S; red[17] = Q;
    }
    __syncthreads();
    float mu = red[16] * (1.f / DIN);
    float var = red[17] * (1.f / DIN) - mu * mu;
    float rs = rsqrtf(var + 1e-5f);
    int mrh = (token >> 3) & 1;
    size_t trow = (size_t)(token >> 4) * NK8;
    int lbase = (token & 7) << 2;
    for (int i = tid; i < DIN; i += 256) {
        float y = (xs[i] - mu) * rs * ln_in_g[i] + ln_in_b[i];
        size_t idx = ((trow + (i >> 3)) << 7) + (((lbase + (i & 3)) << 2) | (mrh + (((i >> 2) & 1) << 1)));
        g_fa[idx] = rna_tf32(y);
    }
}

// ---------------- K4: frag-layout tf32 GEMM + balanced window writer -------
#define STG_F 8192                 // floats per stage
#define SMEM_TOTAL_G (3 * STG_F * 4)
__global__ __launch_bounds__(256, 2) void k_gemm8(const float* __restrict__ bias,
                                                  const float* __restrict__ h,
                                                  float* __restrict__ out) {
    extern __shared__ float sm[];
    uint32_t sb = (uint32_t)__cvta_generic_to_shared(sm);
    int tid = threadIdx.x;
    int bx = blockIdx.x;                 // 0..15
    int m0 = blockIdx.y * 128;
    int warp = tid >> 5, lane = tid & 31;
    int wm = (warp & 1) * 64, wn = (warp >> 1) * 32;
    int grp = lane >> 2, tig = lane & 3;

    float acc[4][4][4];
#pragma unroll
    for (int i = 0; i < 4; i++)
#pragma unroll
        for (int j = 0; j < 4; j++)
#pragma unroll
            for (int r = 0; r < 4; r++) acc[i][j][r] = 0.f;

    int aidx[4], soffA[4], bidx[4], soffB[4];
#pragma unroll
    for (int p = 0; p < 4; p++) {
        int lin = p * 256 + tid;
        int tileA = lin >> 5, chA = lin & 31;          // A: 32 tiles x 512B
        aidx[p] = (((m0 >> 4) + (tileA >> 2)) * NK8 + (tileA & 3)) * 128 + chA * 4;
        soffA[p] = tileA * 512 + chA * 16;
        int tileB = lin >> 5, chB = lin & 31;          // B: 32 superblocks x 512B
        bidx[p] = ((bx * 8 + (tileB >> 2)) * NK8 + (tileB & 3)) * 128 + chB * 4;
        soffB[p] = 16384 + tileB * 512 + chB * 16;
    }

    auto load_stage = [&](int s, int kt) {
        uint32_t base = sb + s * (STG_F * 4);
#pragma unroll
        for (int p = 0; p < 4; p++) {
            cp16(base + soffA[p], g_fa  + (size_t)aidx[p] + (size_t)kt * 512);
            cp16(base + soffB[p], g_bwf + (size_t)bidx[p] + (size_t)kt * 512);
        }
    };

#pragma unroll
    for (int s = 0; s < 2; s++) { load_stage(s, s); CP_COMMIT(); }

    for (int kt = 0; kt < 44; kt++) {
        CP_WAIT1();
        __syncthreads();
        if (kt + 2 < 44) load_stage((kt + 2) % 3, kt + 2);
        CP_COMMIT();
        const float* st = sm + (kt % 3) * STG_F;
#pragma unroll
        for (int kb = 0; kb < 4; kb++) {
            uint4 afr[4];
            uint4 bq[2];
#pragma unroll
            for (int mi = 0; mi < 4; mi++)
                afr[mi] = *(const uint4*)(st + ((((wm >> 4) + mi) << 2) + kb) * 128 + (lane << 2));
#pragma unroll
            for (int np = 0; np < 2; np++)
                bq[np] = *(const uint4*)(st + 4096 + ((((wn >> 4) + np) << 2) + kb) * 128 + (lane << 2));
#pragma unroll
            for (int mi = 0; mi < 4; mi++) {
#pragma unroll
                for (int ni = 0; ni < 4; ni++) {
                    uint32_t b0 = (ni & 1) ? bq[ni >> 1].z : bq[ni >> 1].x;
                    uint32_t b1 = (ni & 1) ? bq[ni >> 1].w : bq[ni >> 1].y;
                    MMA_TF32(acc[mi][ni][0], acc[mi][ni][1], acc[mi][ni][2], acc[mi][ni][3],
                             afr[mi].x, afr[mi].y, afr[mi].z, afr[mi].w, b0, b1);
                }
            }
        }
    }

    // ---- epilogue: gamma -> smem, then beta warps build z -> out slot 0 ----
    __syncthreads();
    float* Gs = sm;                         // [128][68]
    if (wn < 64) {
#pragma unroll
        for (int ni = 0; ni < 4; ni++) {
            int cl = wn + ni * 8 + tig * 2;
            int gcol = bx * 64 + cl;
            float bi0 = bias[gcol], bi1 = bias[gcol + 1];
#pragma unroll
            for (int mi = 0; mi < 4; mi++) {
                int rl = wm + mi * 16 + grp;
                Gs[rl * 68 + cl]       = acc[mi][ni][0] + bi0;
                Gs[rl * 68 + cl + 1]   = acc[mi][ni][1] + bi1;
                Gs[(rl + 8) * 68 + cl]     = acc[mi][ni][2] + bi0;
                Gs[(rl + 8) * 68 + cl + 1] = acc[mi][ni][3] + bi1;
            }
        }
    }
    __syncthreads();
    if (wn >= 64) {
#pragma unroll
        for (int ni = 0; ni < 4; ni++) {
            int cb = wn - 64 + ni * 8 + tig * 2;
            int gcol = bx * 64 + cb;
            float bb0 = bias[1024 + gcol], bb1 = bias[1024 + gcol + 1];
#pragma unroll
            for (int mi = 0; mi < 4; mi++) {
#pragma unroll
                for (int half = 0; half < 2; half++) {
                    int rl = wm + mi * 16 + grp + half * 8;
                    int token = m0 + rl;
                    float2 l2 = *(const float2*)&g_lnh[(size_t)token * DD + gcol];
                    float ga0 = Gs[rl * 68 + cb], ga1 = Gs[rl * 68 + cb + 1];
                    float2 z2;
                    z2.x = l2.x * (1.f + ga0) + acc[mi][ni][half * 2]     + bb0;
                    z2.y = l2.y * (1.f + ga1) + acc[mi][ni][half * 2 + 1] + bb1;
                    __stcs((float2*)&out[(size_t)token * 18432 + gcol], z2);
                }
            }
        }
    }

    // ---- balanced fused window writer ------------------------------------
    // every block: full slot j=bx (out slot 1+bx) for its 128 tokens,
    // plus rows [8*bx, 8*bx+8) of slot j=16 (out slot 17).
    {
        int bb2 = m0 >> 11;
        {
            int j = bx;                               // 0..15
            for (int r = 0; r < 128; r++) {
                int token = m0 + r;
                int t = token & (TT - 1);
                int srct = min(max(t + j - 8, 0), TT - 1);
                float4 v = *(const float4*)&h[((size_t)(bb2 * TT + srct)) * DD + tid * 4];
                __stcs((float4*)&out[(size_t)token * 18432 + (size_t)(1 + j) * DD + tid * 4], v);
            }
        }
        {
            int r0 = bx * 8;                          // slot 17 share
            for (int r = r0; r < r0 + 8; r++) {
                int token = m0 + r;
                int t = token & (TT - 1);
                int srct = min(t + 8, TT - 1);        // j=16 -> t+8, clamped
                float4 v = *(const float4*)&h[((size_t)(bb2 * TT + srct)) * DD + tid * 4];
                __stcs((float4*)&out[(size_t)token * 18432 + (size_t)17 * DD + tid * 4], v);
            }
        }
    }
}

// ---------------------------------------------------------------------------
extern "C" void kernel_launch(void* const* d_in, const int* in_sizes, int n_in,
                              void* d_out, int out_size) {
    const float* h        = (const float*)d_in[0];
    const float* bound_w  = (const float*)d_in[1];
    const float* bound_b  = (const float*)d_in[2];
    const float* conv_w   = (const float*)d_in[3];
    const float* conv_b   = (const float*)d_in[4];
    const float* e0       = (const float*)d_in[5];
    const float* e1       = (const float*)d_in[6];
    const float* key_emb  = (const float*)d_in[7];
    const float* key_w    = (const float*)d_in[8];
    const float* key_b    = (const float*)d_in[9];
    const float* ln_in_g  = (const float*)d_in[10];
    const float* ln_in_b  = (const float*)d_in[11];
    const float* film_w   = (const float*)d_in[12];
    const float* film_b   = (const float*)d_in[13];
    const float* ln_h_g   = (const float*)d_in[14];
    const float* ln_h_b   = (const float*)d_in[15];
    float* out = (float*)d_out;

    cudaFuncSetAttribute(k_gemm8, cudaFuncAttributeMaxDynamicSharedMemorySize, SMEM_TOTAL_G);

    k_roundBt<<<(128 * NK8) / 8, 256>>>(film_w);
    k1       <<<NTOK / 32, 256>>>(h, key_w, key_b, bound_w, bound_b);
    k_film   <<<NTOK, 256>>>(h, conv_w, conv_b, e0, e1, key_emb, ln_in_g, ln_in_b, ln_h_g, ln_h_b);
    k_gemm8  <<<dim3(16, NTOK / 128), 256, SMEM_TOTAL_G>>>(film_b, h, out);
}

// round 13
// speedup vs baseline: 1.0436x; 1.0195x over previous
#include <cuda_runtime.h>
#include <cstdint>
#include <cstddef>

#define TT   2048
#define DD   1024
#define NTOK 8192      // B*T
#define KVN  48
#define DIN  1408
#define NN   2048      // 2*D
#define NK8  176       // DIN/8

// ---------------- scratch (device globals: allocation-free) ----------------
__device__ float g_blog[NTOK];
__device__ float g_keylog[NTOK * KVN];
__device__ float g_lnh[(size_t)NTOK * DD];
__device__ float g_fa[(size_t)NTOK * DIN];    // film_in in A-fragment order
__device__ float g_bwf[(size_t)NN * DIN];     // film_w tf32, permuted, PAIRED B-frag order

__device__ __forceinline__ float rna_tf32(float x) {
    uint32_t u;
    asm("cvt.rna.tf32.f32 %0, %1;" : "=r"(u) : "f"(x));
    return __uint_as_float(u);
}

__device__ __forceinline__ void cp16(uint32_t dst, const void* src) {
    asm volatile("cp.async.cg.shared.global [%0], [%1], 16;" :: "r"(dst), "l"(src));
}
#define CP_COMMIT() asm volatile("cp.async.commit_group;")
#define CP_WAIT1()  asm volatile("cp.async.wait_group 1;")

#define MMA_TF32(d0,d1,d2,d3,a0,a1,a2,a3,b0,b1)                              \
  asm volatile("mma.sync.aligned.m16n8k8.row.col.f32.tf32.tf32.f32 "         \
    "{%0,%1,%2,%3},{%4,%5,%6,%7},{%8,%9},{%0,%1,%2,%3};\n"                   \
    : "+f"(d0), "+f"(d1), "+f"(d2), "+f"(d3)                                 \
    : "r"(a0), "r"(a1), "r"(a2), "r"(a3), "r"(b0), "r"(b1))

// ---------------- K0: film_w -> tf32, permuted, PAIRED B-frag superblocks --
__global__ __launch_bounds__(256) void k_roundBt(const float* __restrict__ film_w) {
    int w = blockIdx.x * 8 + (threadIdx.x >> 5);   // superblock id = P*NK8 + kt8
    int lane = threadIdx.x & 31;
    int kt8 = w % NK8, P = w / NK8;                // P < 128
    int prow0 = P * 16 + (lane >> 2);
    int prow1 = prow0 + 8;
    int k = kt8 * 8 + (lane & 3);
    int g20 = prow0 >> 7, r0 = prow0 & 127;
    int n0 = (r0 < 64) ? (g20 * 64 + r0) : (1024 + g20 * 64 + (r0 - 64));
    int g21 = prow1 >> 7, r1 = prow1 & 127;
    int n1 = (r1 < 64) ? (g21 * 64 + r1) : (1024 + g21 * 64 + (r1 - 64));
    float4 o;
    o.x = rna_tf32(film_w[(size_t)k * NN + n0]);
    o.y = rna_tf32(film_w[(size_t)(k + 4) * NN + n0]);
    o.z = rna_tf32(film_w[(size_t)k * NN + n1]);
    o.w = rna_tf32(film_w[(size_t)(k + 4) * NN + n1]);
    *(float4*)&g_bwf[((size_t)w << 7) + (lane << 2)] = o;
}

// ---------------- K1: key logits + boundary logits (R8 proven form) --------
__global__ __launch_bounds__(256) void k1(const float* __restrict__ h,
                                          const float* __restrict__ key_w,
                                          const float* __restrict__ key_b,
                                          const float* __restrict__ bound_w,
                                          const float* __restrict__ bound_b) {
    __shared__ float hs[32][128];
    __shared__ float ws[128][49];
    __shared__ float bw[128];
    int tid = threadIdx.x;
    int tok0 = blockIdx.x * 32;
    int tg = tid >> 4;
    int ob = (tid & 15) * 3;
    int btok = tid >> 3;
    int be0 = (tid & 7) * 16;
    float a00 = 0.f, a01 = 0.f, a02 = 0.f, a10 = 0.f, a11 = 0.f, a12 = 0.f;
    float bacc = 0.f;
    for (int c = 0; c < 8; c++) {
#pragma unroll
        for (int k2 = 0; k2 < 4; k2++) {
            int idx = tid + k2 * 256;
            int row = idx >> 5, colv = idx & 31;
            *(float4*)&hs[row][colv * 4] =
                *(const float4*)&h[(size_t)(tok0 + row) * DD + c * 128 + colv * 4];
        }
#pragma unroll
        for (int k2 = 0; k2 < 24; k2++) {
            int idx = tid + k2 * 256;
            int d = idx / 48, kk = idx - d * 48;
            ws[d][kk] = key_w[(size_t)(c * 128 + d) * KVN + kk];
        }
        if (tid < 128) bw[tid] = bound_w[c * 128 + tid];
        __syncthreads();
#pragma unroll 4
        for (int d4 = 0; d4 < 32; d4++) {
            float4 ha = *(float4*)&hs[tg][d4 * 4];
            float4 hb = *(float4*)&hs[tg + 16][d4 * 4];
            float hav[4] = {ha.x, ha.y, ha.z, ha.w};
            float hbv[4] = {hb.x, hb.y, hb.z, hb.w};
#pragma unroll
            for (int j = 0; j < 4; j++) {
                int d = d4 * 4 + j;
                float w0 = ws[d][ob], w1 = ws[d][ob + 1], w2 = ws[d][ob + 2];
                a00 += hav[j] * w0; a01 += hav[j] * w1; a02 += hav[j] * w2;
                a10 += hbv[j] * w0; a11 += hbv[j] * w1; a12 += hbv[j] * w2;
            }
        }
        {
            float p = 0.f;
#pragma unroll
            for (int e = 0; e < 16; e++) p += hs[btok][be0 + e] * bw[be0 + e];
#pragma unroll
            for (int o = 4; o; o >>= 1) p += __shfl_xor_sync(0xffffffffu, p, o);
            bacc += p;
        }
        __syncthreads();
    }
    float kb0 = key_b[ob], kb1 = key_b[ob + 1], kb2 = key_b[ob + 2];
    size_t o0 = (size_t)(tok0 + tg) * KVN + ob;
    size_t o1 = (size_t)(tok0 + tg + 16) * KVN + ob;
    g_keylog[o0] = a00 + kb0; g_keylog[o0 + 1] = a01 + kb1; g_keylog[o0 + 2] = a02 + kb2;
    g_keylog[o1] = a10 + kb0; g_keylog[o1 + 1] = a11 + kb1; g_keylog[o1 + 2] = a12 + kb2;
    if ((tid & 7) == 0) g_blog[tok0 + btok] = bacc + bound_b[0];
}

// ---------------- K3: conv+sigmoid + softmax/ek/eb + two layernorms --------
__global__ __launch_bounds__(256) void k_film(const float* __restrict__ h,
                                              const float* __restrict__ conv_w,
                                              const float* __restrict__ conv_b,
                                              const float* __restrict__ e0,
                                              const float* __restrict__ e1,
                                              const float* __restrict__ key_emb,
                                              const float* __restrict__ ln_in_g,
                                              const float* __restrict__ ln_in_b,
                                              const float* __restrict__ ln_h_g,
                                              const float* __restrict__ ln_h_b) {
    __shared__ float xs[DIN];
    __shared__ float kl[KVN];
    __shared__ float red[20];
    __shared__ float s_bs;
    int tid = threadIdx.x, lane = tid & 31, warp = tid >> 5;
    int token = blockIdx.x;

    if (tid == 0) {
        int b = token >> 11, t = token & (TT - 1);
        float s = 0.f;
#pragma unroll
        for (int j = 0; j < 9; j++) {
            int tt = t + j - 4;
            if (tt >= 0 && tt < TT) s += conv_w[j] * g_blog[b * TT + tt];
        }
        s += conv_b[0];
        s_bs = 1.f / (1.f + __expf(-s));
    }

    float4 hv = *(const float4*)&h[(size_t)token * DD + tid * 4];
    *(float4*)&xs[tid * 4] = hv;
    float ps = hv.x + hv.y + hv.z + hv.w;
    float pq = hv.x * hv.x + hv.y * hv.y + hv.z * hv.z + hv.w * hv.w;

    float s = ps, q = pq;
#pragma unroll
    for (int o = 16; o; o >>= 1) {
        s += __shfl_xor_sync(0xffffffffu, s, o);
        q += __shfl_xor_sync(0xffffffffu, q, o);
    }
    if (lane == 0) { red[warp] = s; red[8 + warp] = q; }
    __syncthreads();
    if (tid == 0) {
        float S = 0.f, Q = 0.f;
        for (int i = 0; i < 8; i++) { S += red[i]; Q += red[8 + i]; }
        red[16] = S; red[17] = Q;
    }
    __syncthreads();
    float muh = red[16] * (1.f / DD);
    float varh = red[17] * (1.f / DD) - muh * muh;
    float rsh = rsqrtf(varh + 1e-5f);
    {
        float4 g4 = *(const float4*)&ln_h_g[tid * 4];
        float4 b4 = *(const float4*)&ln_h_b[tid * 4];
        float4 z4;
        z4.x = (hv.x - muh) * rsh * g4.x + b4.x;
        z4.y = (hv.y - muh) * rsh * g4.y + b4.y;
        z4.z = (hv.z - muh) * rsh * g4.z + b4.z;
        z4.w = (hv.w - muh) * rsh * g4.w + b4.w;
        *(float4*)&g_lnh[(size_t)token * DD + tid * 4] = z4;
    }

    if (tid < KVN) kl[tid] = g_keylog[(size_t)token * KVN + tid];
    __syncthreads();
    if (warp == 0) {
        float m = kl[lane];
        if (lane < 16) m = fmaxf(m, kl[32 + lane]);
#pragma unroll
        for (int o = 16; o; o >>= 1) m = fmaxf(m, __shfl_xor_sync(0xffffffffu, m, o));
        if (lane == 0) red[18] = m;
    }
    __syncthreads();
    float mx = red[18];
    if (tid < KVN) kl[tid] = __expf(kl[tid] - mx);
    __syncthreads();
    if (warp == 0) {
        float sm2 = kl[lane] + (lane < 16 ? kl[32 + lane] : 0.f);
#pragma unroll
        for (int o = 16; o; o >>= 1) sm2 += __shfl_xor_sync(0xffffffffu, sm2, o);
        if (lane == 0) red[19] = 1.f / sm2;
    }
    __syncthreads();
    float sinv = red[19];

    if (tid < 128) {
        float a = 0.f;
#pragma unroll
        for (int k = 0; k < KVN; k++) a += kl[k] * key_emb[k * 128 + tid];
        xs[1280 + tid] = a * sinv;
    }
    float bs = s_bs;
    xs[1024 + tid] = bs * e1[tid] + (1.f - bs) * e0[tid];
    __syncthreads();

    float ts = xs[1024 + tid], tq = ts * ts;
    if (tid < 128) { float v = xs[1280 + tid]; ts += v; tq += v * v; }
    s = ps + ts; q = pq + tq;
#pragma unroll
    for (int o = 16; o; o >>= 1) {
        s += __shfl_xor_sync(0xffffffffu, s, o);
        q += __shfl_xor_sync(0xffffffffu, q, o);
    }
    if (lane == 0) { red[warp] = s; red[8 + warp] = q; }
    __syncthreads();
    if (tid == 0) {
        float S = 0.f, Q = 0.f;
        for (int i = 0; i < 8; i++) { S += red[i]; Q += red[8 + i]; }
        red[16] = S; red[17] = Q;
    }
    __syncthreads();
    float mu = red[16] * (1.f / DIN);
    float var = red[17] * (1.f / DIN) - mu * mu;
    float rs = rsqrtf(var + 1e-5f);
    int mrh = (token >> 3) & 1;
    size_t trow = (size_t)(token >> 4) * NK8;
    int lbase = (token & 7) << 2;
    for (int i = tid; i < DIN; i += 256) {
        float y = (xs[i] - mu) * rs * ln_in_g[i] + ln_in_b[i];
        size_t idx = ((trow + (i >> 3)) << 7) + (((lbase + (i & 3)) << 2) | (mrh + (((i >> 2) & 1) << 1)));
        g_fa[idx] = rna_tf32(y);
    }
}

// ---------------- K4: frag-layout tf32 GEMM + balanced window writer -------
#define STG_F 8192                 // floats per stage
#define SMEM_TOTAL_G (3 * STG_F * 4)
__global__ __launch_bounds__(256, 2) void k_gemm8(const float* __restrict__ bias,
                                                  const float* __restrict__ h,
                                                  float* __restrict__ out) {
    extern __shared__ float sm[];
    uint32_t sb = (uint32_t)__cvta_generic_to_shared(sm);
    int tid = threadIdx.x;
    int bx = blockIdx.x;                 // 0..15
    int m0 = blockIdx.y * 128;
    int warp = tid >> 5, lane = tid & 31;
    int wm = (warp & 1) * 64, wn = (warp >> 1) * 32;
    int grp = lane >> 2, tig = lane & 3;

    float acc[4][4][4];
#pragma unroll
    for (int i = 0; i < 4; i++)
#pragma unroll
        for (int j = 0; j < 4; j++)
#pragma unroll
            for (int r = 0; r < 4; r++) acc[i][j][r] = 0.f;

    int aidx[4], soffA[4], bidx[4], soffB[4];
#pragma unroll
    for (int p = 0; p < 4; p++) {
        int lin = p * 256 + tid;
        int tileA = lin >> 5, chA = lin & 31;          // A: 32 tiles x 512B
        aidx[p] = (((m0 >> 4) + (tileA >> 2)) * NK8 + (tileA & 3)) * 128 + chA * 4;
        soffA[p] = tileA * 512 + chA * 16;
        int tileB = lin >> 5, chB = lin & 31;          // B: 32 superblocks x 512B
        bidx[p] = ((bx * 8 + (tileB >> 2)) * NK8 + (tileB & 3)) * 128 + chB * 4;
        soffB[p] = 16384 + tileB * 512 + chB * 16;
    }

    auto load_stage = [&](int s, int kt) {
        uint32_t base = sb + s * (STG_F * 4);
#pragma unroll
        for (int p = 0; p < 4; p++) {
            cp16(base + soffA[p], g_fa  + (size_t)aidx[p] + (size_t)kt * 512);
            cp16(base + soffB[p], g_bwf + (size_t)bidx[p] + (size_t)kt * 512);
        }
    };

#pragma unroll
    for (int s = 0; s < 2; s++) { load_stage(s, s); CP_COMMIT(); }

    for (int kt = 0; kt < 44; kt++) {
        CP_WAIT1();
        __syncthreads();
        if (kt + 2 < 44) load_stage((kt + 2) % 3, kt + 2);
        CP_COMMIT();
        const float* st = sm + (kt % 3) * STG_F;
#pragma unroll
        for (int kb = 0; kb < 4; kb++) {
            uint4 afr[4];
            uint4 bq[2];
#pragma unroll
            for (int mi = 0; mi < 4; mi++)
                afr[mi] = *(const uint4*)(st + ((((wm >> 4) + mi) << 2) + kb) * 128 + (lane << 2));
#pragma unroll
            for (int np = 0; np < 2; np++)
                bq[np] = *(const uint4*)(st + 4096 + ((((wn >> 4) + np) << 2) + kb) * 128 + (lane << 2));
#pragma unroll
            for (int mi = 0; mi < 4; mi++) {
#pragma unroll
                for (int ni = 0; ni < 4; ni++) {
                    uint32_t b0 = (ni & 1) ? bq[ni >> 1].z : bq[ni >> 1].x;
                    uint32_t b1 = (ni & 1) ? bq[ni >> 1].w : bq[ni >> 1].y;
                    MMA_TF32(acc[mi][ni][0], acc[mi][ni][1], acc[mi][ni][2], acc[mi][ni][3],
                             afr[mi].x, afr[mi].y, afr[mi].z, afr[mi].w, b0, b1);
                }
            }
        }
    }

    // ---- epilogue: gamma -> smem, then beta warps build z -> out slot 0 ----
    __syncthreads();
    float* Gs = sm;                         // [128][68]
    if (wn < 64) {
#pragma unroll
        for (int ni = 0; ni < 4; ni++) {
            int cl = wn + ni * 8 + tig * 2;
            int gcol = bx * 64 + cl;
            float bi0 = bias[gcol], bi1 = bias[gcol + 1];
#pragma unroll
            for (int mi = 0; mi < 4; mi++) {
                int rl = wm + mi * 16 + grp;
                Gs[rl * 68 + cl]       = acc[mi][ni][0] + bi0;
                Gs[rl * 68 + cl + 1]   = acc[mi][ni][1] + bi1;
                Gs[(rl + 8) * 68 + cl]     = acc[mi][ni][2] + bi0;
                Gs[(rl + 8) * 68 + cl + 1] = acc[mi][ni][3] + bi1;
            }
        }
    }
    __syncthreads();
    if (wn >= 64) {
#pragma unroll
        for (int ni = 0; ni < 4; ni++) {
            int cb = wn - 64 + ni * 8 + tig * 2;
            int gcol = bx * 64 + cb;
            float bb0 = bias[1024 + gcol], bb1 = bias[1024 + gcol + 1];
#pragma unroll
            for (int mi = 0; mi < 4; mi++) {
#pragma unroll
                for (int half = 0; half < 2; half++) {
                    int rl = wm + mi * 16 + grp + half * 8;
                    int token = m0 + rl;
                    float2 l2 = *(const float2*)&g_lnh[(size_t)token * DD + gcol];
                    float ga0 = Gs[rl * 68 + cb], ga1 = Gs[rl * 68 + cb + 1];
                    float2 z2;
                    z2.x = l2.x * (1.f + ga0) + acc[mi][ni][half * 2]     + bb0;
                    z2.y = l2.y * (1.f + ga1) + acc[mi][ni][half * 2 + 1] + bb1;
                    __stcs((float2*)&out[(size_t)token * 18432 + gcol], z2);
                }
            }
        }
    }

    // ---- balanced fused window writer ------------------------------------
    // every block: full slot j=bx (out slot 1+bx) for its 128 tokens,
    // plus rows [8*bx, 8*bx+8) of slot j=16 (out slot 17).
    {
        int bb2 = m0 >> 11;
        {
            int j = bx;                               // 0..15
            for (int r = 0; r < 128; r++) {
                int token = m0 + r;
                int t = token & (TT - 1);
                int srct = min(max(t + j - 8, 0), TT - 1);
                float4 v = *(const float4*)&h[((size_t)(bb2 * TT + srct)) * DD + tid * 4];
                __stcs((float4*)&out[(size_t)token * 18432 + (size_t)(1 + j) * DD + tid * 4], v);
            }
        }
        {
            int r0 = bx * 8;                          // slot 17 share
            for (int r = r0; r < r0 + 8; r++) {
                int token = m0 + r;
                int t = token & (TT - 1);
                int srct = min(t + 8, TT - 1);        // j=16 -> t+8, clamped
                float4 v = *(const float4*)&h[((size_t)(bb2 * TT + srct)) * DD + tid * 4];
                __stcs((float4*)&out[(size_t)token * 18432 + (size_t)17 * DD + tid * 4], v);
            }
        }
    }
}

// ---------------------------------------------------------------------------
extern "C" void kernel_launch(void* const* d_in, const int* in_sizes, int n_in,
                              void* d_out, int out_size) {
    const float* h        = (const float*)d_in[0];
    const float* bound_w  = (const float*)d_in[1];
    const float* bound_b  = (const float*)d_in[2];
    const float* conv_w   = (const float*)d_in[3];
    const float* conv_b   = (const float*)d_in[4];
    const float* e0       = (const float*)d_in[5];
    const float* e1       = (const float*)d_in[6];
    const float* key_emb  = (const float*)d_in[7];
    const float* key_w    = (const float*)d_in[8];
    const float* key_b    = (const float*)d_in[9];
    const float* ln_in_g  = (const float*)d_in[10];
    const float* ln_in_b  = (const float*)d_in[11];
    const float* film_w   = (const float*)d_in[12];
    const float* film_b   = (const float*)d_in[13];
    const float* ln_h_g   = (const float*)d_in[14];
    const float* ln_h_b   = (const float*)d_in[15];
    float* out = (float*)d_out;

    cudaFuncSetAttribute(k_gemm8, cudaFuncAttributeMaxDynamicSharedMemorySize, SMEM_TOTAL_G);

    k_roundBt<<<(128 * NK8) / 8, 256>>>(film_w);
    k1       <<<NTOK / 32, 256>>>(h, key_w, key_b, bound_w, bound_b);
    k_film   <<<NTOK, 256>>>(h, conv_w, conv_b, e0, e1, key_emb, ln_in_g, ln_in_b, ln_h_g, ln_h_b);
    k_gemm8  <<<dim3(16, NTOK / 128), 256, SMEM_TOTAL_G>>>(film_b, h, out);
}

// round 14
// speedup vs baseline: 1.1232x; 1.0763x over previous
#include <cuda_runtime.h>
#include <cstdint>
#include <cstddef>

#define TT   2048
#define DD   1024
#define NTOK 8192      // B*T
#define KVN  48
#define DIN  1408
#define NN   2048      // 2*D
#define NK8  176       // DIN/8

// ---------------- scratch (device globals: allocation-free) ----------------
__device__ float g_blog[NTOK];
__device__ float g_keylog[NTOK * KVN];
__device__ float g_lnh[(size_t)NTOK * DD];
__device__ float g_fa[(size_t)NTOK * DIN];    // film_in in A-fragment order
__device__ float g_bwf[(size_t)NN * DIN];     // film_w tf32, permuted, PAIRED B-frag order
__device__ float g_w2f[64 * 1024];            // [key_w | bound_w | 0] tf32, PAIRED B-frag order

__device__ __forceinline__ float rna_tf32(float x) {
    uint32_t u;
    asm("cvt.rna.tf32.f32 %0, %1;" : "=r"(u) : "f"(x));
    return __uint_as_float(u);
}

__device__ __forceinline__ void cp16(uint32_t dst, const void* src) {
    asm volatile("cp.async.cg.shared.global [%0], [%1], 16;" :: "r"(dst), "l"(src));
}
#define CP_COMMIT() asm volatile("cp.async.commit_group;")
#define CP_WAIT1()  asm volatile("cp.async.wait_group 1;")

#define MMA_TF32(d0,d1,d2,d3,a0,a1,a2,a3,b0,b1)                              \
  asm volatile("mma.sync.aligned.m16n8k8.row.col.f32.tf32.tf32.f32 "         \
    "{%0,%1,%2,%3},{%4,%5,%6,%7},{%8,%9},{%0,%1,%2,%3};\n"                   \
    : "+f"(d0), "+f"(d1), "+f"(d2), "+f"(d3)                                 \
    : "r"(a0), "r"(a1), "r"(a2), "r"(a3), "r"(b0), "r"(b1))

// ---------------- K0: film_w -> tf32, permuted, PAIRED B-frag superblocks --
__global__ __launch_bounds__(256) void k_roundBt(const float* __restrict__ film_w) {
    int w = blockIdx.x * 8 + (threadIdx.x >> 5);   // superblock id = P*NK8 + kt8
    int lane = threadIdx.x & 31;
    int kt8 = w % NK8, P = w / NK8;                // P < 128
    int prow0 = P * 16 + (lane >> 2);
    int prow1 = prow0 + 8;
    int k = kt8 * 8 + (lane & 3);
    int g20 = prow0 >> 7, r0 = prow0 & 127;
    int n0 = (r0 < 64) ? (g20 * 64 + r0) : (1024 + g20 * 64 + (r0 - 64));
    int g21 = prow1 >> 7, r1 = prow1 & 127;
    int n1 = (r1 < 64) ? (g21 * 64 + r1) : (1024 + g21 * 64 + (r1 - 64));
    float4 o;
    o.x = rna_tf32(film_w[(size_t)k * NN + n0]);
    o.y = rna_tf32(film_w[(size_t)(k + 4) * NN + n0]);
    o.z = rna_tf32(film_w[(size_t)k * NN + n1]);
    o.w = rna_tf32(film_w[(size_t)(k + 4) * NN + n1]);
    *(float4*)&g_bwf[((size_t)w << 7) + (lane << 2)] = o;
}

// ---------------- K0b: [key_w | bound_w | 0] -> tf32 PAIRED B-frag ---------
// W2[k][n]: n<48 -> key_w[k*48+n]; n==48 -> bound_w[k]; n>48 -> 0
// superblock w = P*128 + kt8 (P<4, kt8<128), same packing as k_roundBt.
__device__ __forceinline__ float w2_at(const float* kw, const float* bw, int k, int n) {
    if (n < KVN) return kw[k * KVN + n];
    if (n == KVN) return bw[k];
    return 0.f;
}
__global__ __launch_bounds__(256) void k_prepW(const float* __restrict__ key_w,
                                               const float* __restrict__ bound_w) {
    int w = blockIdx.x * 8 + (threadIdx.x >> 5);   // 0..511
    int lane = threadIdx.x & 31;
    int kt8 = w & 127, P = w >> 7;
    int prow0 = P * 16 + (lane >> 2);
    int prow1 = prow0 + 8;
    int k = kt8 * 8 + (lane & 3);
    float4 o;
    o.x = rna_tf32(w2_at(key_w, bound_w, k, prow0));
    o.y = rna_tf32(w2_at(key_w, bound_w, k + 4, prow0));
    o.z = rna_tf32(w2_at(key_w, bound_w, k, prow1));
    o.w = rna_tf32(w2_at(key_w, bound_w, k + 4, prow1));
    *(float4*)&g_w2f[((size_t)w << 7) + (lane << 2)] = o;
}

// ---------------- K1: tensor-core key+boundary logits ----------------------
// C[8192x64] = h[8192x1024] @ W2[1024x64]; CTA 128 tokens x 64 cols, K=1024.
// 8 warps: wm=(warp&3)*32, wn=(warp>>2)*32; warp tile 32x32.
// Stage: A 16KB (swizzled rows of 32 floats) + B 8KB (superblocks), 3 stages.
#define K1_STG_F 6144
#define K1_SMEM (3 * K1_STG_F * 4)
__global__ __launch_bounds__(256, 1) void k1_tc(const float* __restrict__ h,
                                                const float* __restrict__ key_b,
                                                const float* __restrict__ bound_b) {
    extern __shared__ float sm[];
    uint32_t sb = (uint32_t)__cvta_generic_to_shared(sm);
    int tid = threadIdx.x, warp = tid >> 5, lane = tid & 31;
    int grp = lane >> 2, tig = lane & 3;
    int wm = (warp & 3) * 32, wn = (warp >> 2) * 32;
    int tok0 = blockIdx.x * 128;

    float acc[2][4][4];
#pragma unroll
    for (int i = 0; i < 2; i++)
#pragma unroll
        for (int j = 0; j < 4; j++)
#pragma unroll
            for (int r = 0; r < 4; r++) acc[i][j][r] = 0.f;

    // cp.async coords
    const float* srcA[4];
    uint32_t dstA[4];
#pragma unroll
    for (int p = 0; p < 4; p++) {
        int c = p * 256 + tid;            // 0..1023
        int row = c >> 3, kc = c & 7;     // 16B chunk kc within 128B row
        srcA[p] = h + (size_t)(tok0 + row) * DD + kc * 4;
        int swz = (kc * 4) ^ ((row & 7) << 2);
        dstA[p] = row * 128 + swz * 4;    // bytes
    }
    size_t srcB[2];
    uint32_t dstB[2];
#pragma unroll
    for (int p = 0; p < 2; p++) {
        int c2 = p * 256 + tid;           // 0..511
        int s = c2 >> 5, inner = c2 & 31; // superblock chunk
        srcB[p] = (size_t)(s >> 2) * 16384 + (s & 3) * 128 + inner * 4;
        dstB[p] = 16384 + c2 * 16;        // bytes
    }

    auto load_stage = [&](int s, int kt) {
        uint32_t base = sb + s * (K1_STG_F * 4);
#pragma unroll
        for (int p = 0; p < 4; p++)
            cp16(base + dstA[p], srcA[p] + kt * 32);
#pragma unroll
        for (int p = 0; p < 2; p++)
            cp16(base + dstB[p], g_w2f + srcB[p] + (size_t)kt * 512);
    };

#pragma unroll
    for (int s = 0; s < 2; s++) { load_stage(s, s); CP_COMMIT(); }

    for (int kt = 0; kt < 32; kt++) {
        CP_WAIT1();
        __syncthreads();
        if (kt + 2 < 32) load_stage((kt + 2) % 3, kt + 2);
        CP_COMMIT();
        const float* st = sm + (kt % 3) * K1_STG_F;
#pragma unroll
        for (int kb = 0; kb < 4; kb++) {
            uint32_t af[2][4];
#pragma unroll
            for (int mi = 0; mi < 2; mi++) {
                int r0 = wm + mi * 16 + grp;
                int r1 = r0 + 8;
                int ck = kb * 8 + tig;
                // reg order: (r0,k),(r0+8,k),(r0,k+4),(r0+8,k+4)
                af[mi][0] = __float_as_uint(rna_tf32(st[r0 * 32 + (ck ^ ((r0 & 7) << 2))]));
                af[mi][1] = __float_as_uint(rna_tf32(st[r1 * 32 + (ck ^ ((r1 & 7) << 2))]));
                af[mi][2] = __float_as_uint(rna_tf32(st[r0 * 32 + ((ck + 4) ^ ((r0 & 7) << 2))]));
                af[mi][3] = __float_as_uint(rna_tf32(st[r1 * 32 + ((ck + 4) ^ ((r1 & 7) << 2))]));
            }
            uint4 bq[2];
#pragma unroll
            for (int np = 0; np < 2; np++)
                bq[np] = *(const uint4*)(st + 4096 + ((((wn >> 4) + np) << 2) + kb) * 128 + (lane << 2));
#pragma unroll
            for (int mi = 0; mi < 2; mi++) {
#pragma unroll
                for (int ni = 0; ni < 4; ni++) {
                    uint32_t b0 = (ni & 1) ? bq[ni >> 1].z : bq[ni >> 1].x;
                    uint32_t b1 = (ni & 1) ? bq[ni >> 1].w : bq[ni >> 1].y;
                    MMA_TF32(acc[mi][ni][0], acc[mi][ni][1], acc[mi][ni][2], acc[mi][ni][3],
                             af[mi][0], af[mi][1], af[mi][2], af[mi][3], b0, b1);
                }
            }
        }
    }

    // epilogue: cols<48 -> keylog (+key_b), col 48 -> blog (+bound_b)
    float bb = bound_b[0];
#pragma unroll
    for (int mi = 0; mi < 2; mi++) {
#pragma unroll
        for (int ni = 0; ni < 4; ni++) {
            int cl = wn + ni * 8 + tig * 2;
#pragma unroll
            for (int half = 0; half < 2; half++) {
                int rl = wm + mi * 16 + grp + half * 8;
                int token = tok0 + rl;
                float v0 = acc[mi][ni][half * 2];
                float v1 = acc[mi][ni][half * 2 + 1];
                if (cl < KVN) {
                    float2 o;
                    o.x = v0 + key_b[cl];
                    o.y = v1 + key_b[cl + 1];
                    *(float2*)&g_keylog[(size_t)token * KVN + cl] = o;
                } else if (cl == KVN) {
                    g_blog[token] = v0 + bb;
                }
            }
        }
    }
}

// ---------------- K3: conv+sigmoid + softmax/ek/eb + two layernorms --------
__global__ __launch_bounds__(256) void k_film(const float* __restrict__ h,
                                              const float* __restrict__ conv_w,
                                              const float* __restrict__ conv_b,
                                              const float* __restrict__ e0,
                                              const float* __restrict__ e1,
                                              const float* __restrict__ key_emb,
                                              const float* __restrict__ ln_in_g,
                                              const float* __restrict__ ln_in_b,
                                              const float* __restrict__ ln_h_g,
                                              const float* __restrict__ ln_h_b) {
    __shared__ float xs[DIN];
    __shared__ float kl[KVN];
    __shared__ float red[20];
    __shared__ float s_bs;
    int tid = threadIdx.x, lane = tid & 31, warp = tid >> 5;
    int token = blockIdx.x;

    if (tid == 0) {
        int b = token >> 11, t = token & (TT - 1);
        float s = 0.f;
#pragma unroll
        for (int j = 0; j < 9; j++) {
            int tt = t + j - 4;
            if (tt >= 0 && tt < TT) s += conv_w[j] * g_blog[b * TT + tt];
        }
        s += conv_b[0];
        s_bs = 1.f / (1.f + __expf(-s));
    }

    float4 hv = *(const float4*)&h[(size_t)token * DD + tid * 4];
    *(float4*)&xs[tid * 4] = hv;
    float ps = hv.x + hv.y + hv.z + hv.w;
    float pq = hv.x * hv.x + hv.y * hv.y + hv.z * hv.z + hv.w * hv.w;

    float s = ps, q = pq;
#pragma unroll
    for (int o = 16; o; o >>= 1) {
        s += __shfl_xor_sync(0xffffffffu, s, o);
        q += __shfl_xor_sync(0xffffffffu, q, o);
    }
    if (lane == 0) { red[warp] = s; red[8 + warp] = q; }
    __syncthreads();
    if (tid == 0) {
        float S = 0.f, Q = 0.f;
        for (int i = 0; i < 8; i++) { S += red[i]; Q += red[8 + i]; }
        red[16] = S; red[17] = Q;
    }
    __syncthreads();
    float muh = red[16] * (1.f / DD);
    float varh = red[17] * (1.f / DD) - muh * muh;
    float rsh = rsqrtf(varh + 1e-5f);
    {
        float4 g4 = *(const float4*)&ln_h_g[tid * 4];
        float4 b4 = *(const float4*)&ln_h_b[tid * 4];
        float4 z4;
        z4.x = (hv.x - muh) * rsh * g4.x + b4.x;
        z4.y = (hv.y - muh) * rsh * g4.y + b4.y;
        z4.z = (hv.z - muh) * rsh * g4.z + b4.z;
        z4.w = (hv.w - muh) * rsh * g4.w + b4.w;
        *(float4*)&g_lnh[(size_t)token * DD + tid * 4] = z4;
    }

    if (tid < KVN) kl[tid] = g_keylog[(size_t)token * KVN + tid];
    __syncthreads();
    if (warp == 0) {
        float m = kl[lane];
        if (lane < 16) m = fmaxf(m, kl[32 + lane]);
#pragma unroll
        for (int o = 16; o; o >>= 1) m = fmaxf(m, __shfl_xor_sync(0xffffffffu, m, o));
        if (lane == 0) red[18] = m;
    }
    __syncthreads();
    float mx = red[18];
    if (tid < KVN) kl[tid] = __expf(kl[tid] - mx);
    __syncthreads();
    if (warp == 0) {
        float sm2 = kl[lane] + (lane < 16 ? kl[32 + lane] : 0.f);
#pragma unroll
        for (int o = 16; o; o >>= 1) sm2 += __shfl_xor_sync(0xffffffffu, sm2, o);
        if (lane == 0) red[19] = 1.f / sm2;
    }
    __syncthreads();
    float sinv = red[19];

    if (tid < 128) {
        float a = 0.f;
#pragma unroll
        for (int k = 0; k < KVN; k++) a += kl[k] * key_emb[k * 128 + tid];
        xs[1280 + tid] = a * sinv;
    }
    float bs = s_bs;
    xs[1024 + tid] = bs * e1[tid] + (1.f - bs) * e0[tid];
    __syncthreads();

    float ts = xs[1024 + tid], tq = ts * ts;
    if (tid < 128) { float v = xs[1280 + tid]; ts += v; tq += v * v; }
    s = ps + ts; q = pq + tq;
#pragma unroll
    for (int o = 16; o; o >>= 1) {
        s += __shfl_xor_sync(0xffffffffu, s, o);
        q += __shfl_xor_sync(0xffffffffu, q, o);
    }
    if (lane == 0) { red[warp] = s; red[8 + warp] = q; }
    __syncthreads();
    if (tid == 0) {
        float S = 0.f, Q = 0.f;
        for (int i = 0; i < 8; i++) { S += red[i]; Q += red[8 + i]; }
        red[16] = S; red[17] = Q;
    }
    __syncthreads();
    float mu = red[16] * (1.f / DIN);
    float var = red[17] * (1.f / DIN) - mu * mu;
    float rs = rsqrtf(var + 1e-5f);
    int mrh = (token >> 3) & 1;
    size_t trow = (size_t)(token >> 4) * NK8;
    int lbase = (token & 7) << 2;
    for (int i = tid; i < DIN; i += 256) {
        float y = (xs[i] - mu) * rs * ln_in_g[i] + ln_in_b[i];
        size_t idx = ((trow + (i >> 3)) << 7) + (((lbase + (i & 3)) << 2) | (mrh + (((i >> 2) & 1) << 1)));
        g_fa[idx] = rna_tf32(y);
    }
}

// ---------------- K4: frag-layout tf32 GEMM + balanced window writer -------
#define STG_F 8192                 // floats per stage
#define SMEM_TOTAL_G (3 * STG_F * 4)
__global__ __launch_bounds__(256, 2) void k_gemm8(const float* __restrict__ bias,
                                                  const float* __restrict__ h,
                                                  float* __restrict__ out) {
    extern __shared__ float sm[];
    uint32_t sb = (uint32_t)__cvta_generic_to_shared(sm);
    int tid = threadIdx.x;
    int bx = blockIdx.x;                 // 0..15
    int m0 = blockIdx.y * 128;
    int warp = tid >> 5, lane = tid & 31;
    int wm = (warp & 1) * 64, wn = (warp >> 1) * 32;
    int grp = lane >> 2, tig = lane & 3;

    float acc[4][4][4];
#pragma unroll
    for (int i = 0; i < 4; i++)
#pragma unroll
        for (int j = 0; j < 4; j++)
#pragma unroll
            for (int r = 0; r < 4; r++) acc[i][j][r] = 0.f;

    int aidx[4], soffA[4], bidx[4], soffB[4];
#pragma unroll
    for (int p = 0; p < 4; p++) {
        int lin = p * 256 + tid;
        int tileA = lin >> 5, chA = lin & 31;          // A: 32 tiles x 512B
        aidx[p] = (((m0 >> 4) + (tileA >> 2)) * NK8 + (tileA & 3)) * 128 + chA * 4;
        soffA[p] = tileA * 512 + chA * 16;
        int tileB = lin >> 5, chB = lin & 31;          // B: 32 superblocks x 512B
        bidx[p] = ((bx * 8 + (tileB >> 2)) * NK8 + (tileB & 3)) * 128 + chB * 4;
        soffB[p] = 16384 + tileB * 512 + chB * 16;
    }

    auto load_stage = [&](int s, int kt) {
        uint32_t base = sb + s * (STG_F * 4);
#pragma unroll
        for (int p = 0; p < 4; p++) {
            cp16(base + soffA[p], g_fa  + (size_t)aidx[p] + (size_t)kt * 512);
            cp16(base + soffB[p], g_bwf + (size_t)bidx[p] + (size_t)kt * 512);
        }
    };

#pragma unroll
    for (int s = 0; s < 2; s++) { load_stage(s, s); CP_COMMIT(); }

    for (int kt = 0; kt < 44; kt++) {
        CP_WAIT1();
        __syncthreads();
        if (kt + 2 < 44) load_stage((kt + 2) % 3, kt + 2);
        CP_COMMIT();
        const float* st = sm + (kt % 3) * STG_F;
#pragma unroll
        for (int kb = 0; kb < 4; kb++) {
            uint4 afr[4];
            uint4 bq[2];
#pragma unroll
            for (int mi = 0; mi < 4; mi++)
                afr[mi] = *(const uint4*)(st + ((((wm >> 4) + mi) << 2) + kb) * 128 + (lane << 2));
#pragma unroll
            for (int np = 0; np < 2; np++)
                bq[np] = *(const uint4*)(st + 4096 + ((((wn >> 4) + np) << 2) + kb) * 128 + (lane << 2));
#pragma unroll
            for (int mi = 0; mi < 4; mi++) {
#pragma unroll
                for (int ni = 0; ni < 4; ni++) {
                    uint32_t b0 = (ni & 1) ? bq[ni >> 1].z : bq[ni >> 1].x;
                    uint32_t b1 = (ni & 1) ? bq[ni >> 1].w : bq[ni >> 1].y;
                    MMA_TF32(acc[mi][ni][0], acc[mi][ni][1], acc[mi][ni][2], acc[mi][ni][3],
                             afr[mi].x, afr[mi].y, afr[mi].z, afr[mi].w, b0, b1);
                }
            }
        }
    }

    // ---- epilogue: gamma -> smem, then beta warps build z -> out slot 0 ----
    __syncthreads();
    float* Gs = sm;                         // [128][68]
    if (wn < 64) {
#pragma unroll
        for (int ni = 0; ni < 4; ni++) {
            int cl = wn + ni * 8 + tig * 2;
            int gcol = bx * 64 + cl;
            float bi0 = bias[gcol], bi1 = bias[gcol + 1];
#pragma unroll
            for (int mi = 0; mi < 4; mi++) {
                int rl = wm + mi * 16 + grp;
                Gs[rl * 68 + cl]       = acc[mi][ni][0] + bi0;
                Gs[rl * 68 + cl + 1]   = acc[mi][ni][1] + bi1;
                Gs[(rl + 8) * 68 + cl]     = acc[mi][ni][2] + bi0;
                Gs[(rl + 8) * 68 + cl + 1] = acc[mi][ni][3] + bi1;
            }
        }
    }
    __syncthreads();
    if (wn >= 64) {
#pragma unroll
        for (int ni = 0; ni < 4; ni++) {
            int cb = wn - 64 + ni * 8 + tig * 2;
            int gcol = bx * 64 + cb;
            float bb0 = bias[1024 + gcol], bb1 = bias[1024 + gcol + 1];
#pragma unroll
            for (int mi = 0; mi < 4; mi++) {
#pragma unroll
                for (int half = 0; half < 2; half++) {
                    int rl = wm + mi * 16 + grp + half * 8;
                    int token = m0 + rl;
                    float2 l2 = *(const float2*)&g_lnh[(size_t)token * DD + gcol];
                    float ga0 = Gs[rl * 68 + cb], ga1 = Gs[rl * 68 + cb + 1];
                    float2 z2;
                    z2.x = l2.x * (1.f + ga0) + acc[mi][ni][half * 2]     + bb0;
                    z2.y = l2.y * (1.f + ga1) + acc[mi][ni][half * 2 + 1] + bb1;
                    __stcs((float2*)&out[(size_t)token * 18432 + gcol], z2);
                }
            }
        }
    }

    // ---- balanced fused window writer ------------------------------------
    {
        int bb2 = m0 >> 11;
        {
            int j = bx;                               // 0..15
            for (int r = 0; r < 128; r++) {
                int token = m0 + r;
                int t = token & (TT - 1);
                int srct = min(max(t + j - 8, 0), TT - 1);
                float4 v = *(const float4*)&h[((size_t)(bb2 * TT + srct)) * DD + tid * 4];
                __stcs((float4*)&out[(size_t)token * 18432 + (size_t)(1 + j) * DD + tid * 4], v);
            }
        }
        {
            int r0 = bx * 8;                          // slot 17 share
            for (int r = r0; r < r0 + 8; r++) {
                int token = m0 + r;
                int t = token & (TT - 1);
                int srct = min(t + 8, TT - 1);        // j=16 -> t+8, clamped
                float4 v = *(const float4*)&h[((size_t)(bb2 * TT + srct)) * DD + tid * 4];
                __stcs((float4*)&out[(size_t)token * 18432 + (size_t)17 * DD + tid * 4], v);
            }
        }
    }
}

// ---------------------------------------------------------------------------
extern "C" void kernel_launch(void* const* d_in, const int* in_sizes, int n_in,
                              void* d_out, int out_size) {
    const float* h        = (const float*)d_in[0];
    const float* bound_w  = (const float*)d_in[1];
    const float* bound_b  = (const float*)d_in[2];
    const float* conv_w   = (const float*)d_in[3];
    const float* conv_b   = (const float*)d_in[4];
    const float* e0       = (const float*)d_in[5];
    const float* e1       = (const float*)d_in[6];
    const float* key_emb  = (const float*)d_in[7];
    const float* key_w    = (const float*)d_in[8];
    const float* key_b    = (const float*)d_in[9];
    const float* ln_in_g  = (const float*)d_in[10];
    const float* ln_in_b  = (const float*)d_in[11];
    const float* film_w   = (const float*)d_in[12];
    const float* film_b   = (const float*)d_in[13];
    const float* ln_h_g   = (const float*)d_in[14];
    const float* ln_h_b   = (const float*)d_in[15];
    float* out = (float*)d_out;

    cudaFuncSetAttribute(k_gemm8, cudaFuncAttributeMaxDynamicSharedMemorySize, SMEM_TOTAL_G);
    cudaFuncSetAttribute(k1_tc,   cudaFuncAttributeMaxDynamicSharedMemorySize, K1_SMEM);

    k_prepW  <<<64, 256>>>(key_w, bound_w);
    k_roundBt<<<(128 * NK8) / 8, 256>>>(film_w);
    k1_tc    <<<NTOK / 128, 256, K1_SMEM>>>(h, key_b, bound_b);
    k_film   <<<NTOK, 256>>>(h, conv_w, conv_b, e0, e1, key_emb, ln_in_g, ln_in_b, ln_h_g, ln_h_b);
    k_gemm8  <<<dim3(16, NTOK / 128), 256, SMEM_TOTAL_G>>>(film_b, h, out);
}

// round 15
// speedup vs baseline: 1.1591x; 1.0320x over previous
#include <cuda_runtime.h>
#include <cstdint>
#include <cstddef>

#define TT   2048
#define DD   1024
#define NTOK 8192      // B*T
#define KVN  48
#define DIN  1408
#define NN   2048      // 2*D
#define NK8  176       // DIN/8

// ---------------- scratch (device globals: allocation-free) ----------------
__device__ float g_blog[NTOK];
__device__ float g_keylog[NTOK * KVN];
__device__ float g_lnh[(size_t)NTOK * DD];
__device__ float g_fa[(size_t)NTOK * DIN];    // film_in in A-fragment order
__device__ float g_bwf[(size_t)NN * DIN];     // film_w tf32, permuted, PAIRED B-frag order
__device__ float g_w2f[64 * 1024];            // [key_w | bound_w | 0] tf32, PAIRED B-frag order

__device__ __forceinline__ float rna_tf32(float x) {
    uint32_t u;
    asm("cvt.rna.tf32.f32 %0, %1;" : "=r"(u) : "f"(x));
    return __uint_as_float(u);
}

__device__ __forceinline__ void cp16(uint32_t dst, const void* src) {
    asm volatile("cp.async.cg.shared.global [%0], [%1], 16;" :: "r"(dst), "l"(src));
}
#define CP_COMMIT() asm volatile("cp.async.commit_group;")
#define CP_WAIT1()  asm volatile("cp.async.wait_group 1;")

#define MMA_TF32(d0,d1,d2,d3,a0,a1,a2,a3,b0,b1)                              \
  asm volatile("mma.sync.aligned.m16n8k8.row.col.f32.tf32.tf32.f32 "         \
    "{%0,%1,%2,%3},{%4,%5,%6,%7},{%8,%9},{%0,%1,%2,%3};\n"                   \
    : "+f"(d0), "+f"(d1), "+f"(d2), "+f"(d3)                                 \
    : "r"(a0), "r"(a1), "r"(a2), "r"(a3), "r"(b0), "r"(b1))

// ---------------- K0: film_w -> tf32, permuted, PAIRED B-frag superblocks --
__global__ __launch_bounds__(256) void k_roundBt(const float* __restrict__ film_w) {
    int w = blockIdx.x * 8 + (threadIdx.x >> 5);   // superblock id = P*NK8 + kt8
    int lane = threadIdx.x & 31;
    int kt8 = w % NK8, P = w / NK8;                // P < 128
    int prow0 = P * 16 + (lane >> 2);
    int prow1 = prow0 + 8;
    int k = kt8 * 8 + (lane & 3);
    int g20 = prow0 >> 7, r0 = prow0 & 127;
    int n0 = (r0 < 64) ? (g20 * 64 + r0) : (1024 + g20 * 64 + (r0 - 64));
    int g21 = prow1 >> 7, r1 = prow1 & 127;
    int n1 = (r1 < 64) ? (g21 * 64 + r1) : (1024 + g21 * 64 + (r1 - 64));
    float4 o;
    o.x = rna_tf32(film_w[(size_t)k * NN + n0]);
    o.y = rna_tf32(film_w[(size_t)(k + 4) * NN + n0]);
    o.z = rna_tf32(film_w[(size_t)k * NN + n1]);
    o.w = rna_tf32(film_w[(size_t)(k + 4) * NN + n1]);
    *(float4*)&g_bwf[((size_t)w << 7) + (lane << 2)] = o;
}

// ---------------- K0b: [key_w | bound_w | 0] -> tf32 PAIRED B-frag ---------
__device__ __forceinline__ float w2_at(const float* kw, const float* bw, int k, int n) {
    if (n < KVN) return kw[k * KVN + n];
    if (n == KVN) return bw[k];
    return 0.f;
}
__global__ __launch_bounds__(256) void k_prepW(const float* __restrict__ key_w,
                                               const float* __restrict__ bound_w) {
    int w = blockIdx.x * 8 + (threadIdx.x >> 5);   // 0..511
    int lane = threadIdx.x & 31;
    int kt8 = w & 127, P = w >> 7;
    int prow0 = P * 16 + (lane >> 2);
    int prow1 = prow0 + 8;
    int k = kt8 * 8 + (lane & 3);
    float4 o;
    o.x = rna_tf32(w2_at(key_w, bound_w, k, prow0));
    o.y = rna_tf32(w2_at(key_w, bound_w, k + 4, prow0));
    o.z = rna_tf32(w2_at(key_w, bound_w, k, prow1));
    o.w = rna_tf32(w2_at(key_w, bound_w, k + 4, prow1));
    *(float4*)&g_w2f[((size_t)w << 7) + (lane << 2)] = o;
}

// ---------------- K1: tensor-core key+boundary logits (proven R13) ---------
#define K1_STG_F 6144
#define K1_SMEM (3 * K1_STG_F * 4)
__global__ __launch_bounds__(256, 1) void k1_tc(const float* __restrict__ h,
                                                const float* __restrict__ key_b,
                                                const float* __restrict__ bound_b) {
    extern __shared__ float sm[];
    uint32_t sb = (uint32_t)__cvta_generic_to_shared(sm);
    int tid = threadIdx.x, warp = tid >> 5, lane = tid & 31;
    int grp = lane >> 2, tig = lane & 3;
    int wm = (warp & 3) * 32, wn = (warp >> 2) * 32;
    int tok0 = blockIdx.x * 128;

    float acc[2][4][4];
#pragma unroll
    for (int i = 0; i < 2; i++)
#pragma unroll
        for (int j = 0; j < 4; j++)
#pragma unroll
            for (int r = 0; r < 4; r++) acc[i][j][r] = 0.f;

    const float* srcA[4];
    uint32_t dstA[4];
#pragma unroll
    for (int p = 0; p < 4; p++) {
        int c = p * 256 + tid;
        int row = c >> 3, kc = c & 7;
        srcA[p] = h + (size_t)(tok0 + row) * DD + kc * 4;
        int swz = (kc * 4) ^ ((row & 7) << 2);
        dstA[p] = row * 128 + swz * 4;
    }
    size_t srcB[2];
    uint32_t dstB[2];
#pragma unroll
    for (int p = 0; p < 2; p++) {
        int c2 = p * 256 + tid;
        int s = c2 >> 5, inner = c2 & 31;
        srcB[p] = (size_t)(s >> 2) * 16384 + (s & 3) * 128 + inner * 4;
        dstB[p] = 16384 + c2 * 16;
    }

    auto load_stage = [&](int s, int kt) {
        uint32_t base = sb + s * (K1_STG_F * 4);
#pragma unroll
        for (int p = 0; p < 4; p++)
            cp16(base + dstA[p], srcA[p] + kt * 32);
#pragma unroll
        for (int p = 0; p < 2; p++)
            cp16(base + dstB[p], g_w2f + srcB[p] + (size_t)kt * 512);
    };

#pragma unroll
    for (int s = 0; s < 2; s++) { load_stage(s, s); CP_COMMIT(); }

    for (int kt = 0; kt < 32; kt++) {
        CP_WAIT1();
        __syncthreads();
        if (kt + 2 < 32) load_stage((kt + 2) % 3, kt + 2);
        CP_COMMIT();
        const float* st = sm + (kt % 3) * K1_STG_F;
#pragma unroll
        for (int kb = 0; kb < 4; kb++) {
            uint32_t af[2][4];
#pragma unroll
            for (int mi = 0; mi < 2; mi++) {
                int r0 = wm + mi * 16 + grp;
                int r1 = r0 + 8;
                int ck = kb * 8 + tig;
                af[mi][0] = __float_as_uint(rna_tf32(st[r0 * 32 + (ck ^ ((r0 & 7) << 2))]));
                af[mi][1] = __float_as_uint(rna_tf32(st[r1 * 32 + (ck ^ ((r1 & 7) << 2))]));
                af[mi][2] = __float_as_uint(rna_tf32(st[r0 * 32 + ((ck + 4) ^ ((r0 & 7) << 2))]));
                af[mi][3] = __float_as_uint(rna_tf32(st[r1 * 32 + ((ck + 4) ^ ((r1 & 7) << 2))]));
            }
            uint4 bq[2];
#pragma unroll
            for (int np = 0; np < 2; np++)
                bq[np] = *(const uint4*)(st + 4096 + ((((wn >> 4) + np) << 2) + kb) * 128 + (lane << 2));
#pragma unroll
            for (int mi = 0; mi < 2; mi++) {
#pragma unroll
                for (int ni = 0; ni < 4; ni++) {
                    uint32_t b0 = (ni & 1) ? bq[ni >> 1].z : bq[ni >> 1].x;
                    uint32_t b1 = (ni & 1) ? bq[ni >> 1].w : bq[ni >> 1].y;
                    MMA_TF32(acc[mi][ni][0], acc[mi][ni][1], acc[mi][ni][2], acc[mi][ni][3],
                             af[mi][0], af[mi][1], af[mi][2], af[mi][3], b0, b1);
                }
            }
        }
    }

    float bb = bound_b[0];
#pragma unroll
    for (int mi = 0; mi < 2; mi++) {
#pragma unroll
        for (int ni = 0; ni < 4; ni++) {
            int cl = wn + ni * 8 + tig * 2;
#pragma unroll
            for (int half = 0; half < 2; half++) {
                int rl = wm + mi * 16 + grp + half * 8;
                int token = tok0 + rl;
                float v0 = acc[mi][ni][half * 2];
                float v1 = acc[mi][ni][half * 2 + 1];
                if (cl < KVN) {
                    float2 o;
                    o.x = v0 + key_b[cl];
                    o.y = v1 + key_b[cl + 1];
                    *(float2*)&g_keylog[(size_t)token * KVN + cl] = o;
                } else if (cl == KVN) {
                    g_blog[token] = v0 + bb;
                }
            }
        }
    }
}

// ---------------- K3: paired-token film prep (coalesced g_fa writes) -------
// block = tokens (t, t+8) of one 16-token A-tile group; warps 0-3 do t,
// warps 4-7 do t+8 via named barriers; joint writer emits full float4 frags.
__global__ __launch_bounds__(256) void k_film2(const float* __restrict__ h,
                                               const float* __restrict__ conv_w,
                                               const float* __restrict__ conv_b,
                                               const float* __restrict__ e0,
                                               const float* __restrict__ e1,
                                               const float* __restrict__ key_emb,
                                               const float* __restrict__ ln_in_g,
                                               const float* __restrict__ ln_in_b,
                                               const float* __restrict__ ln_h_g,
                                               const float* __restrict__ ln_h_b) {
    __shared__ float xs[2][DIN];
    __shared__ float kl[2][KVN];
    __shared__ float red[2][16];
    __shared__ float s_bs[2];
    int tid = threadIdx.x;
    int half = tid >> 7;          // 0: token t, 1: token t+8
    int wg = tid & 127;
    int lane = tid & 31;
    int w4 = (tid >> 5) & 3;      // warp within half
    int group = blockIdx.x >> 3;  // 16-token group
    int sub = blockIdx.x & 7;
    int token = group * 16 + sub + half * 8;

#define HBAR() asm volatile("bar.sync %0, 128;" :: "r"(1 + half) : "memory")

    // conv9 + sigmoid (one thread per half)
    if (wg == 0) {
        int b = token >> 11, t = token & (TT - 1);
        float s = 0.f;
#pragma unroll
        for (int j = 0; j < 9; j++) {
            int tt = t + j - 4;
            if (tt >= 0 && tt < TT) s += conv_w[j] * g_blog[b * TT + tt];
        }
        s += conv_b[0];
        s_bs[half] = 1.f / (1.f + __expf(-s));
    }

    // h load: 8 contiguous floats per thread
    float4 hv0 = *(const float4*)&h[(size_t)token * DD + wg * 8];
    float4 hv1 = *(const float4*)&h[(size_t)token * DD + wg * 8 + 4];
    *(float4*)&xs[half][wg * 8] = hv0;
    *(float4*)&xs[half][wg * 8 + 4] = hv1;
    float ps = hv0.x + hv0.y + hv0.z + hv0.w + hv1.x + hv1.y + hv1.z + hv1.w;
    float pq = hv0.x * hv0.x + hv0.y * hv0.y + hv0.z * hv0.z + hv0.w * hv0.w
             + hv1.x * hv1.x + hv1.y * hv1.y + hv1.z * hv1.z + hv1.w * hv1.w;

    // reduce 1: h stats
    float s = ps, q = pq;
#pragma unroll
    for (int o = 16; o; o >>= 1) {
        s += __shfl_xor_sync(0xffffffffu, s, o);
        q += __shfl_xor_sync(0xffffffffu, q, o);
    }
    if (lane == 0) { red[half][w4] = s; red[half][4 + w4] = q; }
    HBAR();
    if (wg == 0) {
        float S = red[half][0] + red[half][1] + red[half][2] + red[half][3];
        float Q = red[half][4] + red[half][5] + red[half][6] + red[half][7];
        red[half][8] = S; red[half][9] = Q;
    }
    HBAR();
    float muh = red[half][8] * (1.f / DD);
    float varh = red[half][9] * (1.f / DD) - muh * muh;
    float rsh = rsqrtf(varh + 1e-5f);
    {
        float4 g0 = *(const float4*)&ln_h_g[wg * 8];
        float4 g1 = *(const float4*)&ln_h_g[wg * 8 + 4];
        float4 b0 = *(const float4*)&ln_h_b[wg * 8];
        float4 b1 = *(const float4*)&ln_h_b[wg * 8 + 4];
        float4 z0, z1;
        z0.x = (hv0.x - muh) * rsh * g0.x + b0.x;
        z0.y = (hv0.y - muh) * rsh * g0.y + b0.y;
        z0.z = (hv0.z - muh) * rsh * g0.z + b0.z;
        z0.w = (hv0.w - muh) * rsh * g0.w + b0.w;
        z1.x = (hv1.x - muh) * rsh * g1.x + b1.x;
        z1.y = (hv1.y - muh) * rsh * g1.y + b1.y;
        z1.z = (hv1.z - muh) * rsh * g1.z + b1.z;
        z1.w = (hv1.w - muh) * rsh * g1.w + b1.w;
        *(float4*)&g_lnh[(size_t)token * DD + wg * 8] = z0;
        *(float4*)&g_lnh[(size_t)token * DD + wg * 8 + 4] = z1;
    }

    // softmax over 48 keys
    if (wg < KVN) kl[half][wg] = g_keylog[(size_t)token * KVN + wg];
    HBAR();
    if (wg < 32) {
        float m = kl[half][lane];
        if (lane < 16) m = fmaxf(m, kl[half][32 + lane]);
#pragma unroll
        for (int o = 16; o; o >>= 1) m = fmaxf(m, __shfl_xor_sync(0xffffffffu, m, o));
        if (lane == 0) red[half][10] = m;
    }
    HBAR();
    float mx = red[half][10];
    if (wg < KVN) kl[half][wg] = __expf(kl[half][wg] - mx);
    HBAR();
    if (wg < 32) {
        float sm2 = kl[half][lane] + (lane < 16 ? kl[half][32 + lane] : 0.f);
#pragma unroll
        for (int o = 16; o; o >>= 1) sm2 += __shfl_xor_sync(0xffffffffu, sm2, o);
        if (lane == 0) red[half][11] = 1.f / sm2;
    }
    HBAR();
    float sinv = red[half][11];

    // ek (dim wg) + eb (dims wg, wg+128)
    float ekv = 0.f;
#pragma unroll
    for (int k = 0; k < KVN; k++) ekv += kl[half][k] * key_emb[k * 128 + wg];
    ekv *= sinv;
    xs[half][1280 + wg] = ekv;
    float bs = s_bs[half];
    float eb0 = bs * e1[wg] + (1.f - bs) * e0[wg];
    float eb1 = bs * e1[128 + wg] + (1.f - bs) * e0[128 + wg];
    xs[half][1024 + wg] = eb0;
    xs[half][1152 + wg] = eb1;

    // reduce 2: concat stats (own tail values, no extra smem reads)
    float ts = eb0 + eb1 + ekv;
    float tq = eb0 * eb0 + eb1 * eb1 + ekv * ekv;
    s = ps + ts; q = pq + tq;
#pragma unroll
    for (int o = 16; o; o >>= 1) {
        s += __shfl_xor_sync(0xffffffffu, s, o);
        q += __shfl_xor_sync(0xffffffffu, q, o);
    }
    if (lane == 0) { red[half][w4] = s; red[half][4 + w4] = q; }
    HBAR();
    if (wg == 0) {
        float S = red[half][0] + red[half][1] + red[half][2] + red[half][3];
        float Q = red[half][4] + red[half][5] + red[half][6] + red[half][7];
        float mu = S * (1.f / DIN);
        float var = Q * (1.f / DIN) - mu * mu;
        red[half][12] = mu;
        red[half][13] = rsqrtf(var + 1e-5f);
    }
    __syncthreads();    // both halves complete; xs[0], xs[1], red valid

    // joint writer: full float4 A-fragments (tokens t -> regs 0,2; t+8 -> 1,3)
    float muA = red[0][12], rsA = red[0][13];
    float muB = red[1][12], rsB = red[1][13];
    size_t tbase = (size_t)group * NK8;
    int lb = sub * 16;                     // float offset of frag run in tile
    for (int j = tid; j < 4 * NK8; j += 256) {
        int T = j >> 2, c = j & 3;
        int i0 = T * 8 + c, i1 = i0 + 4;
        float gg0 = ln_in_g[i0], bb0 = ln_in_b[i0];
        float gg1 = ln_in_g[i1], bb1 = ln_in_b[i1];
        float4 o;
        o.x = rna_tf32((xs[0][i0] - muA) * rsA * gg0 + bb0);
        o.y = rna_tf32((xs[1][i0] - muB) * rsB * gg0 + bb0);
        o.z = rna_tf32((xs[0][i1] - muA) * rsA * gg1 + bb1);
        o.w = rna_tf32((xs[1][i1] - muB) * rsB * gg1 + bb1);
        *(float4*)&g_fa[((tbase + T) << 7) + lb + c * 4] = o;
    }
#undef HBAR
}

// ---------------- K4: frag-layout tf32 GEMM + balanced window writer -------
#define STG_F 8192                 // floats per stage
#define SMEM_TOTAL_G (3 * STG_F * 4)
__global__ __launch_bounds__(256, 2) void k_gemm8(const float* __restrict__ bias,
                                                  const float* __restrict__ h,
                                                  float* __restrict__ out) {
    extern __shared__ float sm[];
    uint32_t sb = (uint32_t)__cvta_generic_to_shared(sm);
    int tid = threadIdx.x;
    int bx = blockIdx.x;                 // 0..15
    int m0 = blockIdx.y * 128;
    int warp = tid >> 5, lane = tid & 31;
    int wm = (warp & 1) * 64, wn = (warp >> 1) * 32;
    int grp = lane >> 2, tig = lane & 3;

    float acc[4][4][4];
#pragma unroll
    for (int i = 0; i < 4; i++)
#pragma unroll
        for (int j = 0; j < 4; j++)
#pragma unroll
            for (int r = 0; r < 4; r++) acc[i][j][r] = 0.f;

    int aidx[4], soffA[4], bidx[4], soffB[4];
#pragma unroll
    for (int p = 0; p < 4; p++) {
        int lin = p * 256 + tid;
        int tileA = lin >> 5, chA = lin & 31;          // A: 32 tiles x 512B
        aidx[p] = (((m0 >> 4) + (tileA >> 2)) * NK8 + (tileA & 3)) * 128 + chA * 4;
        soffA[p] = tileA * 512 + chA * 16;
        int tileB = lin >> 5, chB = lin & 31;          // B: 32 superblocks x 512B
        bidx[p] = ((bx * 8 + (tileB >> 2)) * NK8 + (tileB & 3)) * 128 + chB * 4;
        soffB[p] = 16384 + tileB * 512 + chB * 16;
    }

    auto load_stage = [&](int s, int kt) {
        uint32_t base = sb + s * (STG_F * 4);
#pragma unroll
        for (int p = 0; p < 4; p++) {
            cp16(base + soffA[p], g_fa  + (size_t)aidx[p] + (size_t)kt * 512);
            cp16(base + soffB[p], g_bwf + (size_t)bidx[p] + (size_t)kt * 512);
        }
    };

#pragma unroll
    for (int s = 0; s < 2; s++) { load_stage(s, s); CP_COMMIT(); }

    for (int kt = 0; kt < 44; kt++) {
        CP_WAIT1();
        __syncthreads();
        if (kt + 2 < 44) load_stage((kt + 2) % 3, kt + 2);
        CP_COMMIT();
        const float* st = sm + (kt % 3) * STG_F;
#pragma unroll
        for (int kb = 0; kb < 4; kb++) {
            uint4 afr[4];
            uint4 bq[2];
#pragma unroll
            for (int mi = 0; mi < 4; mi++)
                afr[mi] = *(const uint4*)(st + ((((wm >> 4) + mi) << 2) + kb) * 128 + (lane << 2));
#pragma unroll
            for (int np = 0; np < 2; np++)
                bq[np] = *(const uint4*)(st + 4096 + ((((wn >> 4) + np) << 2) + kb) * 128 + (lane << 2));
#pragma unroll
            for (int mi = 0; mi < 4; mi++) {
#pragma unroll
                for (int ni = 0; ni < 4; ni++) {
                    uint32_t b0 = (ni & 1) ? bq[ni >> 1].z : bq[ni >> 1].x;
                    uint32_t b1 = (ni & 1) ? bq[ni >> 1].w : bq[ni >> 1].y;
                    MMA_TF32(acc[mi][ni][0], acc[mi][ni][1], acc[mi][ni][2], acc[mi][ni][3],
                             afr[mi].x, afr[mi].y, afr[mi].z, afr[mi].w, b0, b1);
                }
            }
        }
    }

    // ---- epilogue: gamma -> smem, then beta warps build z -> out slot 0 ----
    __syncthreads();
    float* Gs = sm;                         // [128][68]
    if (wn < 64) {
#pragma unroll
        for (int ni = 0; ni < 4; ni++) {
            int cl = wn + ni * 8 + tig * 2;
            int gcol = bx * 64 + cl;
            float bi0 = bias[gcol], bi1 = bias[gcol + 1];
#pragma unroll
            for (int mi = 0; mi < 4; mi++) {
                int rl = wm + mi * 16 + grp;
                Gs[rl * 68 + cl]       = acc[mi][ni][0] + bi0;
                Gs[rl * 68 + cl + 1]   = acc[mi][ni][1] + bi1;
                Gs[(rl + 8) * 68 + cl]     = acc[mi][ni][2] + bi0;
                Gs[(rl + 8) * 68 + cl + 1] = acc[mi][ni][3] + bi1;
            }
        }
    }
    __syncthreads();
    if (wn >= 64) {
#pragma unroll
        for (int ni = 0; ni < 4; ni++) {
            int cb = wn - 64 + ni * 8 + tig * 2;
            int gcol = bx * 64 + cb;
            float bb0 = bias[1024 + gcol], bb1 = bias[1024 + gcol + 1];
#pragma unroll
            for (int mi = 0; mi < 4; mi++) {
#pragma unroll
                for (int half = 0; half < 2; half++) {
                    int rl = wm + mi * 16 + grp + half * 8;
                    int token = m0 + rl;
                    float2 l2 = *(const float2*)&g_lnh[(size_t)token * DD + gcol];
                    float ga0 = Gs[rl * 68 + cb], ga1 = Gs[rl * 68 + cb + 1];
                    float2 z2;
                    z2.x = l2.x * (1.f + ga0) + acc[mi][ni][half * 2]     + bb0;
                    z2.y = l2.y * (1.f + ga1) + acc[mi][ni][half * 2 + 1] + bb1;
                    __stcs((float2*)&out[(size_t)token * 18432 + gcol], z2);
                }
            }
        }
    }

    // ---- balanced fused window writer ------------------------------------
    {
        int bb2 = m0 >> 11;
        {
            int j = bx;                               // 0..15
            for (int r = 0; r < 128; r++) {
                int token = m0 + r;
                int t = token & (TT - 1);
                int srct = min(max(t + j - 8, 0), TT - 1);
                float4 v = *(const float4*)&h[((size_t)(bb2 * TT + srct)) * DD + tid * 4];
                __stcs((float4*)&out[(size_t)token * 18432 + (size_t)(1 + j) * DD + tid * 4], v);
            }
        }
        {
            int r0 = bx * 8;                          // slot 17 share
            for (int r = r0; r < r0 + 8; r++) {
                int token = m0 + r;
                int t = token & (TT - 1);
                int srct = min(t + 8, TT - 1);        // j=16 -> t+8, clamped
                float4 v = *(const float4*)&h[((size_t)(bb2 * TT + srct)) * DD + tid * 4];
                __stcs((float4*)&out[(size_t)token * 18432 + (size_t)17 * DD + tid * 4], v);
            }
        }
    }
}

// ---------------------------------------------------------------------------
extern "C" void kernel_launch(void* const* d_in, const int* in_sizes, int n_in,
                              void* d_out, int out_size) {
    const float* h        = (const float*)d_in[0];
    const float* bound_w  = (const float*)d_in[1];
    const float* bound_b  = (const float*)d_in[2];
    const float* conv_w   = (const float*)d_in[3];
    const float* conv_b   = (const float*)d_in[4];
    const float* e0       = (const float*)d_in[5];
    const float* e1       = (const float*)d_in[6];
    const float* key_emb  = (const float*)d_in[7];
    const float* key_w    = (const float*)d_in[8];
    const float* key_b    = (const float*)d_in[9];
    const float* ln_in_g  = (const float*)d_in[10];
    const float* ln_in_b  = (const float*)d_in[11];
    const float* film_w   = (const float*)d_in[12];
    const float* film_b   = (const float*)d_in[13];
    const float* ln_h_g   = (const float*)d_in[14];
    const float* ln_h_b   = (const float*)d_in[15];
    float* out = (float*)d_out;

    cudaFuncSetAttribute(k_gemm8, cudaFuncAttributeMaxDynamicSharedMemorySize, SMEM_TOTAL_G);
    cudaFuncSetAttribute(k1_tc,   cudaFuncAttributeMaxDynamicSharedMemorySize, K1_SMEM);

    k_prepW  <<<64, 256>>>(key_w, bound_w);
    k_roundBt<<<(128 * NK8) / 8, 256>>>(film_w);
    k1_tc    <<<NTOK / 128, 256, K1_SMEM>>>(h, key_b, bound_b);
    k_film2  <<<NTOK / 2, 256>>>(h, conv_w, conv_b, e0, e1, key_emb, ln_in_g, ln_in_b, ln_h_g, ln_h_b);
    k_gemm8  <<<dim3(16, NTOK / 128), 256, SMEM_TOTAL_G>>>(film_b, h, out);
}